// round 4
// baseline (speedup 1.0000x reference)
#include <cuda_runtime.h>
#include <cstdint>

#define N_NODES     500000
#define N_INC       2000000
#define N_HEDGES    100000
#define N_GRAPHS    512
#define CH          64
#define FULLM       0xffffffffu

// ---------------- scratch (device globals; no allocation allowed) ----------------
__device__ __align__(256) float g_xt[(long)N_NODES * CH];    // 128 MB  (xt / t2)
__device__ __align__(256) float g_m [(long)N_HEDGES * CH];   // 25.6 MB (m / m2)
__device__ int   g_degN[N_NODES];
__device__ int   g_degE[N_HEDGES];
__device__ int   g_rowptr[N_NODES + 1];     // node -> edges
__device__ int   g_colptr[N_HEDGES + 1];    // edge -> nodes
__device__ int   g_cursor[N_NODES];
__device__ int   g_cursorE[N_HEDGES];
__device__ int   g_csr[N_INC];              // edge ids, grouped by node
__device__ int   g_csrE[N_INC];             // node ids, grouped by edge
__device__ int   g_bsums[512];
__device__ int   g_bsumsE[512];
__device__ float g_gsum[N_GRAPHS];
__device__ int   g_gcnt[N_GRAPHS];

// ---------------- packed f32x2 helpers ----------------
__device__ __forceinline__ unsigned long long pk2(float v) {
    unsigned long long r;
    asm("mov.b64 %0, {%1, %1};" : "=l"(r) : "f"(v));
    return r;
}
__device__ __forceinline__ unsigned long long pkab(float a, float b) {
    unsigned long long r;
    asm("mov.b64 %0, {%1, %2};" : "=l"(r) : "f"(a), "f"(b));
    return r;
}
__device__ __forceinline__ float2 upk(unsigned long long v) {
    float2 r;
    asm("mov.b64 {%0, %1}, %2;" : "=f"(r.x), "=f"(r.y) : "l"(v));
    return r;
}
__device__ __forceinline__ void fma2(unsigned long long& acc, unsigned long long a, unsigned long long b) {
    asm("fma.rn.f32x2 %0, %1, %2, %0;" : "+l"(acc) : "l"(a), "l"(b));
}

// ---------------- zero scratch (only what must be zero) ----------------
__global__ void k_zero() {
    int t = blockIdx.x * blockDim.x + threadIdx.x;
    int S = gridDim.x * blockDim.x;
    for (int j = t; j < N_NODES; j += S) { g_degN[j] = 0; g_cursor[j] = 0; }
    for (int j = t; j < N_HEDGES; j += S) { g_degE[j] = 0; g_cursorE[j] = 0; }
    for (int j = t; j < N_GRAPHS; j += S) { g_gsum[j] = 0.f; g_gcnt[j] = 0; }
}

// ---------------- degree histograms + graph-size histogram ----------------
__global__ void k_hist(const int* __restrict__ row, const int* __restrict__ col,
                       const int* __restrict__ batch) {
    int i = blockIdx.x * blockDim.x + threadIdx.x;
    if (i < N_INC) {
        atomicAdd(&g_degN[row[i]], 1);
        atomicAdd(&g_degE[col[i]], 1);
    }
    unsigned act = __ballot_sync(FULLM, i < N_NODES);
    if (i < N_NODES) {
        int g = batch[i];
        unsigned mask = __match_any_sync(act, g);
        int leader = __ffs(mask) - 1;
        if ((threadIdx.x & 31) == leader) atomicAdd(&g_gcnt[g], __popc(mask));
    }
}

// ---------------- generic exclusive scan (mode 0: nodes, mode 1: hyperedges) ----------------
__global__ void k_scan1(int mode) {
    const int* __restrict__ in = mode ? g_degE : g_degN;
    int* __restrict__ out = mode ? g_colptr : g_rowptr;
    int* __restrict__ bsum = mode ? g_bsumsE : g_bsums;
    int n = mode ? N_HEDGES : N_NODES;
    __shared__ int sh[1024];
    int tid = threadIdx.x;
    int i = blockIdx.x * 1024 + tid;
    int v = (i < n) ? in[i] : 0;
    sh[tid] = v;
    __syncthreads();
#pragma unroll
    for (int off = 1; off < 1024; off <<= 1) {
        int t = (tid >= off) ? sh[tid - off] : 0;
        __syncthreads();
        sh[tid] += t;
        __syncthreads();
    }
    if (i < n) out[i] = sh[tid] - v;
    if (tid == 1023) bsum[blockIdx.x] = sh[1023];
}

__global__ void k_scan2(int mode, int nblocks) {
    int* __restrict__ bsum = mode ? g_bsumsE : g_bsums;
    __shared__ int sh[512];
    int tid = threadIdx.x;
    int v = (tid < nblocks) ? bsum[tid] : 0;
    sh[tid] = v;
    __syncthreads();
#pragma unroll
    for (int off = 1; off < 512; off <<= 1) {
        int t = (tid >= off) ? sh[tid - off] : 0;
        __syncthreads();
        sh[tid] += t;
        __syncthreads();
    }
    if (tid < nblocks) bsum[tid] = sh[tid] - v;
}

__global__ void k_scan3(int mode) {
    int* __restrict__ out = mode ? g_colptr : g_rowptr;
    const int* __restrict__ bsum = mode ? g_bsumsE : g_bsums;
    int n = mode ? N_HEDGES : N_NODES;
    int i = blockIdx.x * 1024 + threadIdx.x;
    if (i < n) out[i] += bsum[blockIdx.x];
    if (i == 0) out[n] = N_INC;
}

// ---------------- fill both CSRs ----------------
__global__ void k_fill(const int* __restrict__ row, const int* __restrict__ col) {
    int i = blockIdx.x * blockDim.x + threadIdx.x;
    if (i < N_INC) {
        int r = row[i], c = col[i];
        int pr = g_rowptr[r] + atomicAdd(&g_cursor[r], 1);
        g_csr[pr] = c;
        int pc = g_colptr[c] + atomicAdd(&g_cursorE[c], 1);
        g_csrE[pc] = r;
    }
}

// ---------------- warp matvec: 4 nodes, lane owns 4 channels, f32x2 accum ----------------
// group grp = lane>>4 owns nodes (base+2*grp, base+2*grp+1) with inputs xa, xb.
__device__ __forceinline__ void matvec4(const float4& xa, const float4& xb,
                                        const float* __restrict__ Ws,
                                        const float* __restrict__ bs,
                                        int grp, int c4,
                                        float fa[4], float fb[4]) {
    unsigned long long ta01 = pkab(bs[c4], bs[c4 + 1]);
    unsigned long long ta23 = pkab(bs[c4 + 2], bs[c4 + 3]);
    unsigned long long tb01 = ta01, tb23 = ta23;
#pragma unroll
    for (int kk = 0; kk < 16; kk++) {
        int src = (grp << 4) + kk;
        float a0 = __shfl_sync(FULLM, xa.x, src);
        float a1 = __shfl_sync(FULLM, xa.y, src);
        float a2 = __shfl_sync(FULLM, xa.z, src);
        float a3 = __shfl_sync(FULLM, xa.w, src);
        float b0 = __shfl_sync(FULLM, xb.x, src);
        float b1 = __shfl_sync(FULLM, xb.y, src);
        float b2 = __shfl_sync(FULLM, xb.z, src);
        float b3 = __shfl_sync(FULLM, xb.w, src);
        float aarr[4] = {a0, a1, a2, a3};
        float barr[4] = {b0, b1, b2, b3};
#pragma unroll
        for (int c = 0; c < 4; c++) {
            ulonglong2 w = *(const ulonglong2*)(Ws + ((kk * 4 + c) * CH + c4));
            unsigned long long x2a = pk2(aarr[c]);
            unsigned long long x2b = pk2(barr[c]);
            fma2(ta01, x2a, w.x);
            fma2(ta23, x2a, w.y);
            fma2(tb01, x2b, w.x);
            fma2(tb23, x2b, w.y);
        }
    }
    float2 p;
    p = upk(ta01); fa[0] = p.x; fa[1] = p.y;
    p = upk(ta23); fa[2] = p.x; fa[3] = p.y;
    p = upk(tb01); fb[0] = p.x; fb[1] = p.y;
    p = upk(tb23); fb[2] = p.x; fb[3] = p.y;
}

// gather node v's messages from m, h = relu(dinv * sum); all lanes get full h
__device__ __forceinline__ void gather_node(const float* __restrict__ src, int v,
                                            int grp, int c4, float h[4]) {
    int beg = g_rowptr[v], deg = g_rowptr[v + 1] - beg;
    float4 acc = make_float4(0.f, 0.f, 0.f, 0.f);
    for (int j = grp; j < deg; j += 2) {
        int e = g_csr[beg + j];
        float4 mv = *(const float4*)(src + (long)e * CH + c4);
        acc.x += mv.x; acc.y += mv.y; acc.z += mv.z; acc.w += mv.w;
    }
    acc.x += __shfl_xor_sync(FULLM, acc.x, 16);
    acc.y += __shfl_xor_sync(FULLM, acc.y, 16);
    acc.z += __shfl_xor_sync(FULLM, acc.z, 16);
    acc.w += __shfl_xor_sync(FULLM, acc.w, 16);
    float di = deg > 0 ? 1.f / (float)deg : 0.f;
    h[0] = fmaxf(di * acc.x, 0.f);
    h[1] = fmaxf(di * acc.y, 0.f);
    h[2] = fmaxf(di * acc.z, 0.f);
    h[3] = fmaxf(di * acc.w, 0.f);
}

// ---------------- k_xt: xt = x W1 + b1, streaming store ----------------
__global__ void __launch_bounds__(256) k_xt(const float* __restrict__ x,
                                            const float* __restrict__ W,
                                            const float* __restrict__ b) {
    __shared__ __align__(16) float Ws[CH * CH];
    __shared__ float bs[CH];
    for (int i = threadIdx.x; i < CH * CH; i += 256) Ws[i] = W[i];
    if (threadIdx.x < CH) bs[threadIdx.x] = b[threadIdx.x];
    __syncthreads();

    int lane = threadIdx.x & 31;
    int warp = blockIdx.x * 8 + (threadIdx.x >> 5);
    int base = warp * 4;                      // N_NODES % 4 == 0
    int grp = lane >> 4, c4 = (lane & 15) * 4;
    int va = base + grp * 2, vb = va + 1;

    float4 xa = *(const float4*)(x + (long)va * CH + c4);
    float4 xb = *(const float4*)(x + (long)vb * CH + c4);
    float fa[4], fb[4];
    matvec4(xa, xb, Ws, bs, grp, c4, fa, fb);

    *(float4*)(g_xt + (long)va * CH + c4) = make_float4(fa[0], fa[1], fa[2], fa[3]);
    *(float4*)(g_xt + (long)vb * CH + c4) = make_float4(fb[0], fb[1], fb[2], fb[3]);
}

// ---------------- k_edge: m_e = binv * sum_{v in e} xt_v  (pure gather, no atomics) ----------------
__global__ void __launch_bounds__(256) k_edge() {
    int lane = threadIdx.x & 31;
    int e = blockIdx.x * 8 + (threadIdx.x >> 5);   // warp per hyperedge; grid exact
    int grp = lane >> 4, c4 = (lane & 15) * 4;

    int beg = g_colptr[e], deg = g_colptr[e + 1] - beg;
    float4 acc = make_float4(0.f, 0.f, 0.f, 0.f);
    for (int j = grp; j < deg; j += 2) {
        int v = g_csrE[beg + j];
        float4 t = *(const float4*)(g_xt + (long)v * CH + c4);
        acc.x += t.x; acc.y += t.y; acc.z += t.z; acc.w += t.w;
    }
    acc.x += __shfl_xor_sync(FULLM, acc.x, 16);
    acc.y += __shfl_xor_sync(FULLM, acc.y, 16);
    acc.z += __shfl_xor_sync(FULLM, acc.z, 16);
    acc.w += __shfl_xor_sync(FULLM, acc.w, 16);
    if (grp == 0) {
        float bi = deg > 0 ? 1.f / (float)deg : 0.f;
        acc.x *= bi; acc.y *= bi; acc.z *= bi; acc.w *= bi;
        *(float4*)(g_m + (long)e * CH + c4) = acc;
    }
}

// ---------------- k_node: gather m, relu, t2 = h W2 + b2 -> g_xt ----------------
__global__ void __launch_bounds__(256) k_node(const float* __restrict__ W,
                                              const float* __restrict__ b) {
    __shared__ __align__(16) float Ws[CH * CH];
    __shared__ float bs[CH];
    for (int i = threadIdx.x; i < CH * CH; i += 256) Ws[i] = W[i];
    if (threadIdx.x < CH) bs[threadIdx.x] = b[threadIdx.x];
    __syncthreads();

    int lane = threadIdx.x & 31;
    int warp = blockIdx.x * 8 + (threadIdx.x >> 5);
    int base = warp * 4;
    int grp = lane >> 4, c4 = (lane & 15) * 4;

    float4 ha = make_float4(0.f, 0.f, 0.f, 0.f);
    float4 hb = ha;
#pragma unroll
    for (int n = 0; n < 4; n++) {
        float h[4];
        gather_node(g_m, base + n, grp, c4, h);
        if ((n >> 1) == grp) {
            if (n & 1) { hb = make_float4(h[0], h[1], h[2], h[3]); }
            else       { ha = make_float4(h[0], h[1], h[2], h[3]); }
        }
    }

    float fa[4], fb[4];
    matvec4(ha, hb, Ws, bs, grp, c4, fa, fb);

    int va = base + grp * 2, vb = va + 1;
    *(float4*)(g_xt + (long)va * CH + c4) = make_float4(fa[0], fa[1], fa[2], fa[3]);
    *(float4*)(g_xt + (long)vb * CH + c4) = make_float4(fb[0], fb[1], fb[2], fb[3]);
}

// ---------------- conv2 pass B + pooling + fc dot ----------------
__global__ void __launch_bounds__(256) k_conv_c(const int* __restrict__ batch,
                                                const float* __restrict__ Wfc) {
    int lane = threadIdx.x & 31;
    int warp = blockIdx.x * 8 + (threadIdx.x >> 5);
    int base = warp * 4;
    int grp = lane >> 4, c4 = (lane & 15) * 4;
    float4 wf = *(const float4*)(Wfc + c4);

    float acc = 0.f;
    int curg = -1;
#pragma unroll
    for (int n = 0; n < 4; n++) {
        int v = base + n;
        float h[4];
        gather_node(g_m, v, grp, c4, h);
        float p = (grp == 0) ? (h[0] * wf.x + h[1] * wf.y + h[2] * wf.z + h[3] * wf.w) : 0.f;
#pragma unroll
        for (int o = 16; o > 0; o >>= 1) p += __shfl_xor_sync(FULLM, p, o);
        if (lane == 0) {
            int g = batch[v];
            if (g != curg) {
                if (curg >= 0) atomicAdd(&g_gsum[curg], acc);
                curg = g;
                acc = 0.f;
            }
            acc += p;
        }
    }
    if (lane == 0 && curg >= 0) atomicAdd(&g_gsum[curg], acc);
}

// ---------------- finalize ----------------
__global__ void k_fin(float* __restrict__ out, const float* __restrict__ bfc) {
    int g = blockIdx.x * blockDim.x + threadIdx.x;
    if (g < N_GRAPHS) {
        float cnt = fmaxf((float)g_gcnt[g], 1.f);
        out[g] = g_gsum[g] / cnt + bfc[0];
    }
}

// ---------------- launch ----------------
extern "C" void kernel_launch(void* const* d_in, const int* in_sizes, int n_in,
                              void* d_out, int out_size) {
    const float* x     = (const float*)d_in[0];
    const int*   eidx  = (const int*)d_in[1];
    const int*   row   = eidx;
    const int*   col   = eidx + N_INC;
    const int*   batch = (const int*)d_in[2];
    const float* W1    = (const float*)d_in[3];
    const float* b1    = (const float*)d_in[4];
    const float* W2    = (const float*)d_in[5];
    const float* b2    = (const float*)d_in[6];
    const float* Wfc   = (const float*)d_in[7];
    const float* bfc   = (const float*)d_in[8];
    float*       out   = (float*)d_out;

    const int NB_INC   = (N_INC + 255) / 256;          // 7813
    const int NB_SCANN = (N_NODES + 1023) / 1024;      // 489
    const int NB_SCANE = (N_HEDGES + 1023) / 1024;     // 98
    const int NB_NODE  = (N_NODES / 4) / 8;            // 15625
    const int NB_EDGE  = N_HEDGES / 8;                 // 12500

    k_zero<<<512, 256>>>();
    k_hist<<<NB_INC, 256>>>(row, col, batch);
    k_scan1<<<NB_SCANN, 1024>>>(0);
    k_scan2<<<1, 512>>>(0, NB_SCANN);
    k_scan3<<<NB_SCANN, 1024>>>(0);
    k_scan1<<<NB_SCANE, 1024>>>(1);
    k_scan2<<<1, 512>>>(1, NB_SCANE);
    k_scan3<<<NB_SCANE, 1024>>>(1);
    k_fill<<<NB_INC, 256>>>(row, col);
    k_xt<<<NB_NODE, 256>>>(x, W1, b1);
    k_edge<<<NB_EDGE, 256>>>();
    k_node<<<NB_NODE, 256>>>(W2, b2);
    k_edge<<<NB_EDGE, 256>>>();
    k_conv_c<<<NB_NODE, 256>>>(batch, Wfc);
    k_fin<<<2, 256>>>(out, bfc);
}

// round 6
// speedup vs baseline: 1.0374x; 1.0374x over previous
#include <cuda_runtime.h>
#include <cuda_bf16.h>
#include <cstdint>

#define N_NODES     500000
#define N_INC       2000000
#define N_HEDGES    100000
#define N_GRAPHS    512
#define CH          64
#define FULLM       0xffffffffu

// ---------------- scratch (device globals; no allocation allowed) ----------------
// bf16 rows: 64ch * 2B = 128B = one cache line. xt_h = 64 MB (L2-resident target
// of the random edge gathers), m_h = 12.8 MB.
__device__ __align__(256) uint32_t g_xt_h[(long)N_NODES * 32];   // 64 MB bf16
__device__ __align__(256) uint32_t g_m_h [(long)N_HEDGES * 32];  // 12.8 MB bf16
__device__ int   g_degN[N_NODES];
__device__ int   g_degE[N_HEDGES];
__device__ int   g_rowptr[N_NODES + 1];     // node -> edges
__device__ int   g_colptr[N_HEDGES + 1];    // edge -> nodes
__device__ int   g_cursor[N_NODES];
__device__ int   g_cursorE[N_HEDGES];
__device__ int   g_csr[N_INC];              // edge ids, grouped by node
__device__ int   g_csrE[N_INC];             // node ids, grouped by edge
__device__ int   g_bsums[512];
__device__ int   g_bsumsE[512];
__device__ float g_gsum[N_GRAPHS];
__device__ int   g_gcnt[N_GRAPHS];

// ---------------- packed f32x2 helpers ----------------
__device__ __forceinline__ unsigned long long pk2(float v) {
    unsigned long long r;
    asm("mov.b64 %0, {%1, %1};" : "=l"(r) : "f"(v));
    return r;
}
__device__ __forceinline__ unsigned long long pkab(float a, float b) {
    unsigned long long r;
    asm("mov.b64 %0, {%1, %2};" : "=l"(r) : "f"(a), "f"(b));
    return r;
}
__device__ __forceinline__ float2 upk(unsigned long long v) {
    float2 r;
    asm("mov.b64 {%0, %1}, %2;" : "=f"(r.x), "=f"(r.y) : "l"(v));
    return r;
}
__device__ __forceinline__ void fma2(unsigned long long& acc, unsigned long long a, unsigned long long b) {
    asm("fma.rn.f32x2 %0, %1, %2, %0;" : "+l"(acc) : "l"(a), "l"(b));
}
__device__ __forceinline__ uint32_t f2_to_bf(float a, float b) {
    uint32_t r;
    asm("cvt.rn.bf16x2.f32 %0, %1, %2;" : "=r"(r) : "f"(b), "f"(a));
    return r;
}
__device__ __forceinline__ float2 bf_to_f2(uint32_t p) {
    return __bfloat1622float2(*reinterpret_cast<const __nv_bfloat162*>(&p));
}

// ---------------- zero scratch (only what must be zero) ----------------
__global__ void k_zero() {
    int t = blockIdx.x * blockDim.x + threadIdx.x;
    int S = gridDim.x * blockDim.x;
    for (int j = t; j < N_NODES; j += S) { g_degN[j] = 0; g_cursor[j] = 0; }
    for (int j = t; j < N_HEDGES; j += S) { g_degE[j] = 0; g_cursorE[j] = 0; }
    for (int j = t; j < N_GRAPHS; j += S) { g_gsum[j] = 0.f; g_gcnt[j] = 0; }
}

// ---------------- degree histograms + graph-size histogram ----------------
__global__ void k_hist(const int* __restrict__ row, const int* __restrict__ col,
                       const int* __restrict__ batch) {
    int i = blockIdx.x * blockDim.x + threadIdx.x;
    if (i < N_INC) {
        atomicAdd(&g_degN[row[i]], 1);
        atomicAdd(&g_degE[col[i]], 1);
    }
    unsigned act = __ballot_sync(FULLM, i < N_NODES);
    if (i < N_NODES) {
        int g = batch[i];
        unsigned mask = __match_any_sync(act, g);
        int leader = __ffs(mask) - 1;
        if ((threadIdx.x & 31) == leader) atomicAdd(&g_gcnt[g], __popc(mask));
    }
}

// ---------------- generic exclusive scan (mode 0: nodes, mode 1: hyperedges) ----------------
__global__ void k_scan1(int mode) {
    const int* __restrict__ in = mode ? g_degE : g_degN;
    int* __restrict__ out = mode ? g_colptr : g_rowptr;
    int* __restrict__ bsum = mode ? g_bsumsE : g_bsums;
    int n = mode ? N_HEDGES : N_NODES;
    __shared__ int sh[1024];
    int tid = threadIdx.x;
    int i = blockIdx.x * 1024 + tid;
    int v = (i < n) ? in[i] : 0;
    sh[tid] = v;
    __syncthreads();
#pragma unroll
    for (int off = 1; off < 1024; off <<= 1) {
        int t = (tid >= off) ? sh[tid - off] : 0;
        __syncthreads();
        sh[tid] += t;
        __syncthreads();
    }
    if (i < n) out[i] = sh[tid] - v;
    if (tid == 1023) bsum[blockIdx.x] = sh[1023];
}

__global__ void k_scan2(int mode, int nblocks) {
    int* __restrict__ bsum = mode ? g_bsumsE : g_bsums;
    __shared__ int sh[512];
    int tid = threadIdx.x;
    int v = (tid < nblocks) ? bsum[tid] : 0;
    sh[tid] = v;
    __syncthreads();
#pragma unroll
    for (int off = 1; off < 512; off <<= 1) {
        int t = (tid >= off) ? sh[tid - off] : 0;
        __syncthreads();
        sh[tid] += t;
        __syncthreads();
    }
    if (tid < nblocks) bsum[tid] = sh[tid] - v;
}

__global__ void k_scan3(int mode) {
    int* __restrict__ out = mode ? g_colptr : g_rowptr;
    const int* __restrict__ bsum = mode ? g_bsumsE : g_bsums;
    int n = mode ? N_HEDGES : N_NODES;
    int i = blockIdx.x * 1024 + threadIdx.x;
    if (i < n) out[i] += bsum[blockIdx.x];
    if (i == 0) out[n] = N_INC;
}

// ---------------- fill both CSRs ----------------
__global__ void k_fill(const int* __restrict__ row, const int* __restrict__ col) {
    int i = blockIdx.x * blockDim.x + threadIdx.x;
    if (i < N_INC) {
        int r = row[i], c = col[i];
        int pr = g_rowptr[r] + atomicAdd(&g_cursor[r], 1);
        g_csr[pr] = c;
        int pc = g_colptr[c] + atomicAdd(&g_cursorE[c], 1);
        g_csrE[pc] = r;
    }
}

// ---------------- warp matvec: 4 nodes, lane owns 4 channels, f32x2 accum ----------------
// group grp = lane>>4 owns nodes (base+2*grp, base+2*grp+1) with inputs xa, xb.
__device__ __forceinline__ void matvec4(const float4& xa, const float4& xb,
                                        const float* __restrict__ Ws,
                                        const float* __restrict__ bs,
                                        int grp, int c4,
                                        float fa[4], float fb[4]) {
    unsigned long long ta01 = pkab(bs[c4], bs[c4 + 1]);
    unsigned long long ta23 = pkab(bs[c4 + 2], bs[c4 + 3]);
    unsigned long long tb01 = ta01, tb23 = ta23;
#pragma unroll
    for (int kk = 0; kk < 16; kk++) {
        int src = (grp << 4) + kk;
        float a0 = __shfl_sync(FULLM, xa.x, src);
        float a1 = __shfl_sync(FULLM, xa.y, src);
        float a2 = __shfl_sync(FULLM, xa.z, src);
        float a3 = __shfl_sync(FULLM, xa.w, src);
        float b0 = __shfl_sync(FULLM, xb.x, src);
        float b1 = __shfl_sync(FULLM, xb.y, src);
        float b2 = __shfl_sync(FULLM, xb.z, src);
        float b3 = __shfl_sync(FULLM, xb.w, src);
        float aarr[4] = {a0, a1, a2, a3};
        float barr[4] = {b0, b1, b2, b3};
#pragma unroll
        for (int c = 0; c < 4; c++) {
            ulonglong2 w = *(const ulonglong2*)(Ws + ((kk * 4 + c) * CH + c4));
            unsigned long long x2a = pk2(aarr[c]);
            unsigned long long x2b = pk2(barr[c]);
            fma2(ta01, x2a, w.x);
            fma2(ta23, x2a, w.y);
            fma2(tb01, x2b, w.x);
            fma2(tb23, x2b, w.y);
        }
    }
    float2 p;
    p = upk(ta01); fa[0] = p.x; fa[1] = p.y;
    p = upk(ta23); fa[2] = p.x; fa[3] = p.y;
    p = upk(tb01); fb[0] = p.x; fb[1] = p.y;
    p = upk(tb23); fb[2] = p.x; fb[3] = p.y;
}

// gather node v's bf16 messages from m_h; h = relu(dinv * sum); all lanes get full h
__device__ __forceinline__ void gather_node(int v, int grp, int c4, float h[4]) {
    int beg = g_rowptr[v], deg = g_rowptr[v + 1] - beg;
    float4 acc = make_float4(0.f, 0.f, 0.f, 0.f);
    for (int j = grp; j < deg; j += 2) {
        int e = g_csr[beg + j];
        uint2 p = *(const uint2*)(g_m_h + (long)e * 32 + (c4 >> 1));
        float2 lo = bf_to_f2(p.x), hi = bf_to_f2(p.y);
        acc.x += lo.x; acc.y += lo.y; acc.z += hi.x; acc.w += hi.y;
    }
    acc.x += __shfl_xor_sync(FULLM, acc.x, 16);
    acc.y += __shfl_xor_sync(FULLM, acc.y, 16);
    acc.z += __shfl_xor_sync(FULLM, acc.z, 16);
    acc.w += __shfl_xor_sync(FULLM, acc.w, 16);
    float di = deg > 0 ? 1.f / (float)deg : 0.f;
    h[0] = fmaxf(di * acc.x, 0.f);
    h[1] = fmaxf(di * acc.y, 0.f);
    h[2] = fmaxf(di * acc.z, 0.f);
    h[3] = fmaxf(di * acc.w, 0.f);
}

// ---------------- k_xt: xt = x W1 + b1, bf16 streaming store ----------------
__global__ void __launch_bounds__(256) k_xt(const float* __restrict__ x,
                                            const float* __restrict__ W,
                                            const float* __restrict__ b) {
    __shared__ __align__(16) float Ws[CH * CH];
    __shared__ float bs[CH];
    for (int i = threadIdx.x; i < CH * CH; i += 256) Ws[i] = W[i];
    if (threadIdx.x < CH) bs[threadIdx.x] = b[threadIdx.x];
    __syncthreads();

    int lane = threadIdx.x & 31;
    int warp = blockIdx.x * 8 + (threadIdx.x >> 5);
    int base = warp * 4;                      // N_NODES % 4 == 0
    int grp = lane >> 4, c4 = (lane & 15) * 4;
    int va = base + grp * 2, vb = va + 1;

    float4 xa = *(const float4*)(x + (long)va * CH + c4);
    float4 xb = *(const float4*)(x + (long)vb * CH + c4);
    float fa[4], fb[4];
    matvec4(xa, xb, Ws, bs, grp, c4, fa, fb);

    *(uint2*)(g_xt_h + (long)va * 32 + (c4 >> 1)) =
        make_uint2(f2_to_bf(fa[0], fa[1]), f2_to_bf(fa[2], fa[3]));
    *(uint2*)(g_xt_h + (long)vb * 32 + (c4 >> 1)) =
        make_uint2(f2_to_bf(fb[0], fb[1]), f2_to_bf(fb[2], fb[3]));
}

// ---------------- k_edge: m_e = binv * sum_{v in e} xt_v  (bf16 gather, L2-resident) ----------------
// warp per hyperedge; lane owns channels (2*lane, 2*lane+1); member ids block-loaded + shfl.
__global__ void __launch_bounds__(256) k_edge() {
    int lane = threadIdx.x & 31;
    int e = blockIdx.x * 8 + (threadIdx.x >> 5);   // grid exact: N_HEDGES/8

    int beg = g_colptr[e], end = g_colptr[e + 1];
    float2 acc = make_float2(0.f, 0.f);
    for (int chunk = beg; chunk < end; chunk += 32) {
        int n = min(32, end - chunk);
        int idx = (lane < n) ? g_csrE[chunk + lane] : 0;
        for (int k = 0; k < n; k++) {
            int v = __shfl_sync(FULLM, idx, k);
            float2 f = bf_to_f2(g_xt_h[(long)v * 32 + lane]);
            acc.x += f.x;
            acc.y += f.y;
        }
    }
    int deg = end - beg;
    float bi = deg > 0 ? 1.f / (float)deg : 0.f;
    g_m_h[(long)e * 32 + lane] = f2_to_bf(acc.x * bi, acc.y * bi);
}

// ---------------- k_node: gather m_h, relu, t2 = h W2 + b2 -> xt_h ----------------
__global__ void __launch_bounds__(256) k_node(const float* __restrict__ W,
                                              const float* __restrict__ b) {
    __shared__ __align__(16) float Ws[CH * CH];
    __shared__ float bs[CH];
    for (int i = threadIdx.x; i < CH * CH; i += 256) Ws[i] = W[i];
    if (threadIdx.x < CH) bs[threadIdx.x] = b[threadIdx.x];
    __syncthreads();

    int lane = threadIdx.x & 31;
    int warp = blockIdx.x * 8 + (threadIdx.x >> 5);
    int base = warp * 4;
    int grp = lane >> 4, c4 = (lane & 15) * 4;

    float4 ha = make_float4(0.f, 0.f, 0.f, 0.f);
    float4 hb = ha;
#pragma unroll
    for (int n = 0; n < 4; n++) {
        float h[4];
        gather_node(base + n, grp, c4, h);
        if ((n >> 1) == grp) {
            if (n & 1) hb = make_float4(h[0], h[1], h[2], h[3]);
            else       ha = make_float4(h[0], h[1], h[2], h[3]);
        }
    }

    float fa[4], fb[4];
    matvec4(ha, hb, Ws, bs, grp, c4, fa, fb);

    int va = base + grp * 2, vb = va + 1;
    *(uint2*)(g_xt_h + (long)va * 32 + (c4 >> 1)) =
        make_uint2(f2_to_bf(fa[0], fa[1]), f2_to_bf(fa[2], fa[3]));
    *(uint2*)(g_xt_h + (long)vb * 32 + (c4 >> 1)) =
        make_uint2(f2_to_bf(fb[0], fb[1]), f2_to_bf(fb[2], fb[3]));
}

// ---------------- conv2 pass B + pooling + fc dot ----------------
__global__ void __launch_bounds__(256) k_conv_c(const int* __restrict__ batch,
                                                const float* __restrict__ Wfc) {
    int lane = threadIdx.x & 31;
    int warp = blockIdx.x * 8 + (threadIdx.x >> 5);
    int base = warp * 4;
    int grp = lane >> 4, c4 = (lane & 15) * 4;
    float4 wf = *(const float4*)(Wfc + c4);

    float acc = 0.f;
    int curg = -1;
#pragma unroll
    for (int n = 0; n < 4; n++) {
        int v = base + n;
        float h[4];
        gather_node(v, grp, c4, h);
        float p = (grp == 0) ? (h[0] * wf.x + h[1] * wf.y + h[2] * wf.z + h[3] * wf.w) : 0.f;
#pragma unroll
        for (int o = 16; o > 0; o >>= 1) p += __shfl_xor_sync(FULLM, p, o);
        if (lane == 0) {
            int g = batch[v];
            if (g != curg) {
                if (curg >= 0) atomicAdd(&g_gsum[curg], acc);
                curg = g;
                acc = 0.f;
            }
            acc += p;
        }
    }
    if (lane == 0 && curg >= 0) atomicAdd(&g_gsum[curg], acc);
}

// ---------------- finalize ----------------
__global__ void k_fin(float* __restrict__ out, const float* __restrict__ bfc) {
    int g = blockIdx.x * blockDim.x + threadIdx.x;
    if (g < N_GRAPHS) {
        float cnt = fmaxf((float)g_gcnt[g], 1.f);
        out[g] = g_gsum[g] / cnt + bfc[0];
    }
}

// ---------------- launch ----------------
extern "C" void kernel_launch(void* const* d_in, const int* in_sizes, int n_in,
                              void* d_out, int out_size) {
    const float* x     = (const float*)d_in[0];
    const int*   eidx  = (const int*)d_in[1];
    const int*   row   = eidx;
    const int*   col   = eidx + N_INC;
    const int*   batch = (const int*)d_in[2];
    const float* W1    = (const float*)d_in[3];
    const float* b1    = (const float*)d_in[4];
    const float* W2    = (const float*)d_in[5];
    const float* b2    = (const float*)d_in[6];
    const float* Wfc   = (const float*)d_in[7];
    const float* bfc   = (const float*)d_in[8];
    float*       out   = (float*)d_out;

    const int NB_INC   = (N_INC + 255) / 256;          // 7813
    const int NB_SCANN = (N_NODES + 1023) / 1024;      // 489
    const int NB_SCANE = (N_HEDGES + 1023) / 1024;     // 98
    const int NB_NODE  = (N_NODES / 4) / 8;            // 15625
    const int NB_EDGE  = N_HEDGES / 8;                 // 12500

    k_zero<<<512, 256>>>();
    k_hist<<<NB_INC, 256>>>(row, col, batch);
    k_scan1<<<NB_SCANN, 1024>>>(0);
    k_scan2<<<1, 512>>>(0, NB_SCANN);
    k_scan3<<<NB_SCANN, 1024>>>(0);
    k_xt<<<NB_NODE, 256>>>(x, W1, b1);      // independent of CSR — 6th launch for ncu -s 5
    k_scan1<<<NB_SCANE, 1024>>>(1);
    k_scan2<<<1, 512>>>(1, NB_SCANE);
    k_scan3<<<NB_SCANE, 1024>>>(1);
    k_fill<<<NB_INC, 256>>>(row, col);
    k_edge<<<NB_EDGE, 256>>>();
    k_node<<<NB_NODE, 256>>>(W2, b2);
    k_edge<<<NB_EDGE, 256>>>();
    k_conv_c<<<NB_NODE, 256>>>(batch, Wfc);
    k_fin<<<2, 256>>>(out, bfc);
}

// round 7
// speedup vs baseline: 1.3407x; 1.2925x over previous
#include <cuda_runtime.h>
#include <cuda_bf16.h>
#include <cstdint>

#define N_NODES     500000
#define N_INC       2000000
#define N_HEDGES    100000
#define N_GRAPHS    512
#define CH          64
#define FULLM       0xffffffffu
#define N_TILES     31250          // N_NODES / 16
#define WSTRIDE     68             // padded smem row stride (conflict-free)

// ---------------- scratch (device globals; no allocation allowed) ----------------
__device__ __align__(256) uint32_t g_xt_h[(long)N_NODES * 32];   // 64 MB bf16 rows (128B each)
__device__ __align__(256) uint32_t g_m_h [(long)N_HEDGES * 32];  // 12.8 MB bf16 rows
__device__ int   g_degN[N_NODES];
__device__ int   g_degE[N_HEDGES];
__device__ int   g_rowptr[N_NODES + 1];     // node -> edges
__device__ int   g_colptr[N_HEDGES + 1];    // edge -> nodes
__device__ int   g_cursor[N_NODES];
__device__ int   g_cursorE[N_HEDGES];
__device__ int   g_csr[N_INC];              // edge ids, grouped by node
__device__ int   g_csrE[N_INC];             // node ids, grouped by edge
__device__ int   g_bsums[512];
__device__ int   g_bsumsE[512];
__device__ float g_gsum[N_GRAPHS];
__device__ int   g_gcnt[N_GRAPHS];

// ---------------- small helpers ----------------
__device__ __forceinline__ uint32_t f2_to_bf(float a, float b) {
    uint32_t r;
    asm("cvt.rn.bf16x2.f32 %0, %1, %2;" : "=r"(r) : "f"(b), "f"(a));
    return r;
}
__device__ __forceinline__ float2 bf_to_f2(uint32_t p) {
    return __bfloat1622float2(*reinterpret_cast<const __nv_bfloat162*>(&p));
}
__device__ __forceinline__ uint32_t tf32r(float f) {
    uint32_t r;
    asm("cvt.rna.tf32.f32 %0, %1;" : "=r"(r) : "f"(f));
    return r;
}
__device__ __forceinline__ void mma_tf32(float c[4],
                                         uint32_t a0, uint32_t a1, uint32_t a2, uint32_t a3,
                                         uint32_t b0, uint32_t b1) {
    asm volatile("mma.sync.aligned.m16n8k8.row.col.f32.tf32.tf32.f32 "
                 "{%0,%1,%2,%3}, {%4,%5,%6,%7}, {%8,%9}, {%0,%1,%2,%3};"
                 : "+f"(c[0]), "+f"(c[1]), "+f"(c[2]), "+f"(c[3])
                 : "r"(a0), "r"(a1), "r"(a2), "r"(a3), "r"(b0), "r"(b1));
}

// ---------------- zero scratch ----------------
__global__ void k_zero() {
    int t = blockIdx.x * blockDim.x + threadIdx.x;
    int S = gridDim.x * blockDim.x;
    for (int j = t; j < N_NODES; j += S) { g_degN[j] = 0; g_cursor[j] = 0; }
    for (int j = t; j < N_HEDGES; j += S) { g_degE[j] = 0; g_cursorE[j] = 0; }
    for (int j = t; j < N_GRAPHS; j += S) { g_gsum[j] = 0.f; g_gcnt[j] = 0; }
}

// ---------------- degree histograms + graph-size histogram ----------------
__global__ void k_hist(const int* __restrict__ row, const int* __restrict__ col,
                       const int* __restrict__ batch) {
    int i = blockIdx.x * blockDim.x + threadIdx.x;
    if (i < N_INC) {
        atomicAdd(&g_degN[row[i]], 1);
        atomicAdd(&g_degE[col[i]], 1);
    }
    unsigned act = __ballot_sync(FULLM, i < N_NODES);
    if (i < N_NODES) {
        int g = batch[i];
        unsigned mask = __match_any_sync(act, g);
        int leader = __ffs(mask) - 1;
        if ((threadIdx.x & 31) == leader) atomicAdd(&g_gcnt[g], __popc(mask));
    }
}

// ---------------- generic exclusive scan (mode 0: nodes, mode 1: hyperedges) ----------------
__global__ void k_scan1(int mode) {
    const int* __restrict__ in = mode ? g_degE : g_degN;
    int* __restrict__ out = mode ? g_colptr : g_rowptr;
    int* __restrict__ bsum = mode ? g_bsumsE : g_bsums;
    int n = mode ? N_HEDGES : N_NODES;
    __shared__ int sh[1024];
    int tid = threadIdx.x;
    int i = blockIdx.x * 1024 + tid;
    int v = (i < n) ? in[i] : 0;
    sh[tid] = v;
    __syncthreads();
#pragma unroll
    for (int off = 1; off < 1024; off <<= 1) {
        int t = (tid >= off) ? sh[tid - off] : 0;
        __syncthreads();
        sh[tid] += t;
        __syncthreads();
    }
    if (i < n) out[i] = sh[tid] - v;
    if (tid == 1023) bsum[blockIdx.x] = sh[1023];
}

__global__ void k_scan2(int mode, int nblocks) {
    int* __restrict__ bsum = mode ? g_bsumsE : g_bsums;
    __shared__ int sh[512];
    int tid = threadIdx.x;
    int v = (tid < nblocks) ? bsum[tid] : 0;
    sh[tid] = v;
    __syncthreads();
#pragma unroll
    for (int off = 1; off < 512; off <<= 1) {
        int t = (tid >= off) ? sh[tid - off] : 0;
        __syncthreads();
        sh[tid] += t;
        __syncthreads();
    }
    if (tid < nblocks) bsum[tid] = sh[tid] - v;
}

__global__ void k_scan3(int mode) {
    int* __restrict__ out = mode ? g_colptr : g_rowptr;
    const int* __restrict__ bsum = mode ? g_bsumsE : g_bsums;
    int n = mode ? N_HEDGES : N_NODES;
    int i = blockIdx.x * 1024 + threadIdx.x;
    if (i < n) out[i] += bsum[blockIdx.x];
    if (i == 0) out[n] = N_INC;
}

// ---------------- fill both CSRs ----------------
__global__ void k_fill(const int* __restrict__ row, const int* __restrict__ col) {
    int i = blockIdx.x * blockDim.x + threadIdx.x;
    if (i < N_INC) {
        int r = row[i], c = col[i];
        int pr = g_rowptr[r] + atomicAdd(&g_cursor[r], 1);
        g_csr[pr] = c;
        int pc = g_colptr[c] + atomicAdd(&g_cursorE[c], 1);
        g_csrE[pc] = r;
    }
}

// ---------------- k_xt: xt = x W1 + b1 via tf32 mma, bf16 store ----------------
// warp = 16 nodes. A frags LDG'd straight from x; W staged [n][k] stride 68 in smem.
__global__ void __launch_bounds__(256) k_xt(const float* __restrict__ x,
                                            const float* __restrict__ W,
                                            const float* __restrict__ b) {
    __shared__ uint32_t Ws[CH * WSTRIDE];   // tf32 bits, [n][k] stride 68
    __shared__ float bs[CH];
    for (int i = threadIdx.x; i < CH * CH; i += 256) {
        int k = i >> 6, n = i & 63;
        Ws[n * WSTRIDE + k] = tf32r(W[i]);
    }
    if (threadIdx.x < CH) bs[threadIdx.x] = b[threadIdx.x];
    __syncthreads();

    int lane = threadIdx.x & 31;
    int tile = blockIdx.x * 8 + (threadIdx.x >> 5);
    if (tile >= N_TILES) return;
    int row0 = tile * 16;
    int g = lane >> 2, t = lane & 3;

    float c[8][4];
#pragma unroll
    for (int nt = 0; nt < 8; nt++) {
        float b0 = bs[nt * 8 + t * 2], b1 = bs[nt * 8 + t * 2 + 1];
        c[nt][0] = b0; c[nt][1] = b1; c[nt][2] = b0; c[nt][3] = b1;
    }

#pragma unroll
    for (int kt = 0; kt < 8; kt++) {
        const float* xp = x + (long)(row0 + g) * CH + kt * 8 + t;
        uint32_t a0 = tf32r(xp[0]);
        uint32_t a2 = tf32r(xp[4]);
        uint32_t a1 = tf32r(xp[8 * CH]);
        uint32_t a3 = tf32r(xp[8 * CH + 4]);
#pragma unroll
        for (int nt = 0; nt < 8; nt++) {
            uint32_t b0 = Ws[(nt * 8 + g) * WSTRIDE + kt * 8 + t];
            uint32_t b1 = Ws[(nt * 8 + g) * WSTRIDE + kt * 8 + t + 4];
            mma_tf32(c[nt], a0, a1, a2, a3, b0, b1);
        }
    }

#pragma unroll
    for (int nt = 0; nt < 8; nt++) {
        g_xt_h[(long)(row0 + g) * 32 + nt * 4 + t]     = f2_to_bf(c[nt][0], c[nt][1]);
        g_xt_h[(long)(row0 + g + 8) * 32 + nt * 4 + t] = f2_to_bf(c[nt][2], c[nt][3]);
    }
}

// ---------------- k_edge: m_e = binv * sum_{v in e} xt_v (bf16 gather, L2-resident) ----------------
__global__ void __launch_bounds__(256) k_edge() {
    int lane = threadIdx.x & 31;
    int e = blockIdx.x * 8 + (threadIdx.x >> 5);   // grid exact: N_HEDGES/8

    int beg = g_colptr[e], end = g_colptr[e + 1];
    float2 acc = make_float2(0.f, 0.f);
    for (int chunk = beg; chunk < end; chunk += 32) {
        int n = min(32, end - chunk);
        int idx = (lane < n) ? g_csrE[chunk + lane] : 0;
        for (int k = 0; k < n; k++) {
            int v = __shfl_sync(FULLM, idx, k);
            float2 f = bf_to_f2(g_xt_h[(long)v * 32 + lane]);
            acc.x += f.x;
            acc.y += f.y;
        }
    }
    int deg = end - beg;
    float bi = deg > 0 ? 1.f / (float)deg : 0.f;
    g_m_h[(long)e * 32 + lane] = f2_to_bf(acc.x * bi, acc.y * bi);
}

// ---------------- k_node: gather m_h -> relu -> mma with W2 -> bf16 store ----------------
// 128 threads (4 warps) to fit static smem. warp = 16 nodes.
__global__ void __launch_bounds__(128) k_node(const float* __restrict__ W,
                                              const float* __restrict__ b) {
    __shared__ uint32_t Ws[CH * WSTRIDE];        // tf32 bits, [n][k] stride 68
    __shared__ float bs[CH];
    __shared__ uint32_t As[4][16 * WSTRIDE];     // per-warp A tile, tf32 bits, stride 68
    for (int i = threadIdx.x; i < CH * CH; i += 128) {
        int k = i >> 6, n = i & 63;
        Ws[n * WSTRIDE + k] = tf32r(W[i]);
    }
    if (threadIdx.x < CH) bs[threadIdx.x] = b[threadIdx.x];
    __syncthreads();

    int lane = threadIdx.x & 31;
    int wid = threadIdx.x >> 5;
    int tile = blockIdx.x * 4 + wid;
    if (tile >= N_TILES) return;
    int row0 = tile * 16;

    // gather phase: whole warp per node; lane owns channels (2*lane, 2*lane+1)
    for (int n = 0; n < 16; n++) {
        int v = row0 + n;
        int beg = g_rowptr[v], deg = g_rowptr[v + 1] - beg;
        float2 acc = make_float2(0.f, 0.f);
        for (int j = 0; j < deg; j++) {
            int e = g_csr[beg + j];          // broadcast load (same addr all lanes)
            float2 f = bf_to_f2(g_m_h[(long)e * 32 + lane]);
            acc.x += f.x;
            acc.y += f.y;
        }
        float di = deg > 0 ? 1.f / (float)deg : 0.f;
        uint32_t h0 = tf32r(fmaxf(acc.x * di, 0.f));
        uint32_t h1 = tf32r(fmaxf(acc.y * di, 0.f));
        *(uint2*)&As[wid][n * WSTRIDE + 2 * lane] = make_uint2(h0, h1);
    }
    __syncwarp();

    // mma phase
    int g = lane >> 2, t = lane & 3;
    float c[8][4];
#pragma unroll
    for (int nt = 0; nt < 8; nt++) {
        float b0 = bs[nt * 8 + t * 2], b1 = bs[nt * 8 + t * 2 + 1];
        c[nt][0] = b0; c[nt][1] = b1; c[nt][2] = b0; c[nt][3] = b1;
    }
#pragma unroll
    for (int kt = 0; kt < 8; kt++) {
        uint32_t a0 = As[wid][g * WSTRIDE + kt * 8 + t];
        uint32_t a1 = As[wid][(g + 8) * WSTRIDE + kt * 8 + t];
        uint32_t a2 = As[wid][g * WSTRIDE + kt * 8 + t + 4];
        uint32_t a3 = As[wid][(g + 8) * WSTRIDE + kt * 8 + t + 4];
#pragma unroll
        for (int nt = 0; nt < 8; nt++) {
            uint32_t b0 = Ws[(nt * 8 + g) * WSTRIDE + kt * 8 + t];
            uint32_t b1 = Ws[(nt * 8 + g) * WSTRIDE + kt * 8 + t + 4];
            mma_tf32(c[nt], a0, a1, a2, a3, b0, b1);
        }
    }
#pragma unroll
    for (int nt = 0; nt < 8; nt++) {
        g_xt_h[(long)(row0 + g) * 32 + nt * 4 + t]     = f2_to_bf(c[nt][0], c[nt][1]);
        g_xt_h[(long)(row0 + g + 8) * 32 + nt * 4 + t] = f2_to_bf(c[nt][2], c[nt][3]);
    }
}

// ---------------- conv2 pass B + pooling + fc dot ----------------
__global__ void __launch_bounds__(256) k_conv_c(const int* __restrict__ batch,
                                                const float* __restrict__ Wfc) {
    int lane = threadIdx.x & 31;
    int warp = blockIdx.x * 8 + (threadIdx.x >> 5);
    int base = warp * 4;
    int grp = lane >> 4, c4 = (lane & 15) * 4;
    float4 wf = *(const float4*)(Wfc + c4);

    float acc = 0.f;
    int curg = -1;
#pragma unroll
    for (int n = 0; n < 4; n++) {
        int v = base + n;
        int beg = g_rowptr[v], deg = g_rowptr[v + 1] - beg;
        float4 s = make_float4(0.f, 0.f, 0.f, 0.f);
        for (int j = grp; j < deg; j += 2) {
            int e = g_csr[beg + j];
            uint2 pw = *(const uint2*)(g_m_h + (long)e * 32 + (c4 >> 1));
            float2 lo = bf_to_f2(pw.x), hi = bf_to_f2(pw.y);
            s.x += lo.x; s.y += lo.y; s.z += hi.x; s.w += hi.y;
        }
        s.x += __shfl_xor_sync(FULLM, s.x, 16);
        s.y += __shfl_xor_sync(FULLM, s.y, 16);
        s.z += __shfl_xor_sync(FULLM, s.z, 16);
        s.w += __shfl_xor_sync(FULLM, s.w, 16);
        float di = deg > 0 ? 1.f / (float)deg : 0.f;
        float p = 0.f;
        if (grp == 0) {
            p = fmaxf(di * s.x, 0.f) * wf.x + fmaxf(di * s.y, 0.f) * wf.y +
                fmaxf(di * s.z, 0.f) * wf.z + fmaxf(di * s.w, 0.f) * wf.w;
        }
#pragma unroll
        for (int o = 16; o > 0; o >>= 1) p += __shfl_xor_sync(FULLM, p, o);
        if (lane == 0) {
            int g = batch[v];
            if (g != curg) {
                if (curg >= 0) atomicAdd(&g_gsum[curg], acc);
                curg = g;
                acc = 0.f;
            }
            acc += p;
        }
    }
    if (lane == 0 && curg >= 0) atomicAdd(&g_gsum[curg], acc);
}

// ---------------- finalize ----------------
__global__ void k_fin(float* __restrict__ out, const float* __restrict__ bfc) {
    int g = blockIdx.x * blockDim.x + threadIdx.x;
    if (g < N_GRAPHS) {
        float cnt = fmaxf((float)g_gcnt[g], 1.f);
        out[g] = g_gsum[g] / cnt + bfc[0];
    }
}

// ---------------- launch ----------------
extern "C" void kernel_launch(void* const* d_in, const int* in_sizes, int n_in,
                              void* d_out, int out_size) {
    const float* x     = (const float*)d_in[0];
    const int*   eidx  = (const int*)d_in[1];
    const int*   row   = eidx;
    const int*   col   = eidx + N_INC;
    const int*   batch = (const int*)d_in[2];
    const float* W1    = (const float*)d_in[3];
    const float* b1    = (const float*)d_in[4];
    const float* W2    = (const float*)d_in[5];
    const float* b2    = (const float*)d_in[6];
    const float* Wfc   = (const float*)d_in[7];
    const float* bfc   = (const float*)d_in[8];
    float*       out   = (float*)d_out;

    const int NB_INC   = (N_INC + 255) / 256;          // 7813
    const int NB_SCANN = (N_NODES + 1023) / 1024;      // 489
    const int NB_SCANE = (N_HEDGES + 1023) / 1024;     // 98
    const int NB_XT    = (N_TILES + 7) / 8;            // 3907 (8 warps/block)
    const int NB_NODE  = (N_TILES + 3) / 4;            // 7813 (4 warps/block)
    const int NB_EDGE  = N_HEDGES / 8;                 // 12500
    const int NB_CONVC = (N_NODES / 4) / 8;            // 15625

    k_zero<<<512, 256>>>();
    k_hist<<<NB_INC, 256>>>(row, col, batch);
    k_scan1<<<NB_SCANN, 1024>>>(0);
    k_xt<<<NB_XT, 256>>>(x, W1, b1);     // position 4 -> gets the ncu capture
    k_scan2<<<1, 512>>>(0, NB_SCANN);
    k_scan3<<<NB_SCANN, 1024>>>(0);
    k_scan1<<<NB_SCANE, 1024>>>(1);
    k_scan2<<<1, 512>>>(1, NB_SCANE);
    k_scan3<<<NB_SCANE, 1024>>>(1);
    k_fill<<<NB_INC, 256>>>(row, col);
    k_edge<<<NB_EDGE, 256>>>();
    k_node<<<NB_NODE, 128>>>(W2, b2);
    k_edge<<<NB_EDGE, 256>>>();
    k_conv_c<<<NB_CONVC, 256>>>(batch, Wfc);
    k_fin<<<2, 256>>>(out, bfc);
}

// round 8
// speedup vs baseline: 1.3653x; 1.0183x over previous
#include <cuda_runtime.h>
#include <cuda_bf16.h>
#include <cstdint>

#define N_NODES     500000
#define N_INC       2000000
#define N_HEDGES    100000
#define N_GRAPHS    512
#define CH          64
#define FULLM       0xffffffffu
#define N_TILES     31250          // N_NODES / 16
#define WSTRIDE     68             // padded smem row stride (conflict-free)

// ---------------- scratch (device globals; no allocation allowed) ----------------
__device__ __align__(256) uint32_t g_xt_h[(long)N_NODES * 32];   // 64 MB bf16 rows (128B each)
__device__ __align__(256) uint32_t g_m_h [(long)N_HEDGES * 32];  // 12.8 MB bf16 rows
__device__ int   g_degN[N_NODES];
__device__ int   g_degE[N_HEDGES];
__device__ int   g_rowptr[N_NODES + 1];     // node -> edges
__device__ int   g_colptr[N_HEDGES + 1];    // edge -> nodes
__device__ int   g_cursor[N_NODES];
__device__ int   g_cursorE[N_HEDGES];
__device__ int   g_csr[N_INC];              // edge ids, grouped by node
__device__ int   g_csrE[N_INC];             // node ids, grouped by edge
__device__ int   g_bsums[512];
__device__ int   g_bsumsE[512];
__device__ float g_gsum[N_GRAPHS];
__device__ int   g_gcnt[N_GRAPHS];

// ---------------- small helpers ----------------
__device__ __forceinline__ uint32_t f2_to_bf(float a, float b) {
    uint32_t r;
    asm("cvt.rn.bf16x2.f32 %0, %1, %2;" : "=r"(r) : "f"(b), "f"(a));
    return r;
}
__device__ __forceinline__ float2 bf_to_f2(uint32_t p) {
    return __bfloat1622float2(*reinterpret_cast<const __nv_bfloat162*>(&p));
}
__device__ __forceinline__ uint32_t tf32r(float f) {
    uint32_t r;
    asm("cvt.rna.tf32.f32 %0, %1;" : "=r"(r) : "f"(f));
    return r;
}
__device__ __forceinline__ void mma_tf32(float c[4],
                                         uint32_t a0, uint32_t a1, uint32_t a2, uint32_t a3,
                                         uint32_t b0, uint32_t b1) {
    asm volatile("mma.sync.aligned.m16n8k8.row.col.f32.tf32.tf32.f32 "
                 "{%0,%1,%2,%3}, {%4,%5,%6,%7}, {%8,%9}, {%0,%1,%2,%3};"
                 : "+f"(c[0]), "+f"(c[1]), "+f"(c[2]), "+f"(c[3])
                 : "r"(a0), "r"(a1), "r"(a2), "r"(a3), "r"(b0), "r"(b1));
}

// ---------------- zero scratch ----------------
__global__ void k_zero() {
    int t = blockIdx.x * blockDim.x + threadIdx.x;
    int S = gridDim.x * blockDim.x;
    for (int j = t; j < N_NODES; j += S) { g_degN[j] = 0; g_cursor[j] = 0; }
    for (int j = t; j < N_HEDGES; j += S) { g_degE[j] = 0; g_cursorE[j] = 0; }
    for (int j = t; j < N_GRAPHS; j += S) { g_gsum[j] = 0.f; g_gcnt[j] = 0; }
}

// ---------------- degree histograms + graph-size histogram ----------------
__global__ void k_hist(const int* __restrict__ row, const int* __restrict__ col,
                       const int* __restrict__ batch) {
    int i = blockIdx.x * blockDim.x + threadIdx.x;
    if (i < N_INC) {
        atomicAdd(&g_degN[row[i]], 1);
        atomicAdd(&g_degE[col[i]], 1);
    }
    unsigned act = __ballot_sync(FULLM, i < N_NODES);
    if (i < N_NODES) {
        int g = batch[i];
        unsigned mask = __match_any_sync(act, g);
        int leader = __ffs(mask) - 1;
        if ((threadIdx.x & 31) == leader) atomicAdd(&g_gcnt[g], __popc(mask));
    }
}

// ---------------- generic exclusive scan (mode 0: nodes, mode 1: hyperedges) ----------------
__global__ void k_scan1(int mode) {
    const int* __restrict__ in = mode ? g_degE : g_degN;
    int* __restrict__ out = mode ? g_colptr : g_rowptr;
    int* __restrict__ bsum = mode ? g_bsumsE : g_bsums;
    int n = mode ? N_HEDGES : N_NODES;
    __shared__ int sh[1024];
    int tid = threadIdx.x;
    int i = blockIdx.x * 1024 + tid;
    int v = (i < n) ? in[i] : 0;
    sh[tid] = v;
    __syncthreads();
#pragma unroll
    for (int off = 1; off < 1024; off <<= 1) {
        int t = (tid >= off) ? sh[tid - off] : 0;
        __syncthreads();
        sh[tid] += t;
        __syncthreads();
    }
    if (i < n) out[i] = sh[tid] - v;
    if (tid == 1023) bsum[blockIdx.x] = sh[1023];
}

__global__ void k_scan2(int mode, int nblocks) {
    int* __restrict__ bsum = mode ? g_bsumsE : g_bsums;
    __shared__ int sh[512];
    int tid = threadIdx.x;
    int v = (tid < nblocks) ? bsum[tid] : 0;
    sh[tid] = v;
    __syncthreads();
#pragma unroll
    for (int off = 1; off < 512; off <<= 1) {
        int t = (tid >= off) ? sh[tid - off] : 0;
        __syncthreads();
        sh[tid] += t;
        __syncthreads();
    }
    if (tid < nblocks) bsum[tid] = sh[tid] - v;
}

__global__ void k_scan3(int mode) {
    int* __restrict__ out = mode ? g_colptr : g_rowptr;
    const int* __restrict__ bsum = mode ? g_bsumsE : g_bsums;
    int n = mode ? N_HEDGES : N_NODES;
    int i = blockIdx.x * 1024 + threadIdx.x;
    if (i < n) out[i] += bsum[blockIdx.x];
    if (i == 0) out[n] = N_INC;
}

// ---------------- fill both CSRs ----------------
__global__ void k_fill(const int* __restrict__ row, const int* __restrict__ col) {
    int i = blockIdx.x * blockDim.x + threadIdx.x;
    if (i < N_INC) {
        int r = row[i], c = col[i];
        int pr = g_rowptr[r] + atomicAdd(&g_cursor[r], 1);
        g_csr[pr] = c;
        int pc = g_colptr[c] + atomicAdd(&g_cursorE[c], 1);
        g_csrE[pc] = r;
    }
}

// ---------------- k_xt: xt = x W1 + b1 via tf32 mma, bf16 store ----------------
// 128 threads / 4 warps; warp = 16 nodes. x tile staged through smem with
// coalesced float4 LDGs (kills the scalar-LDG L1 wavefront storm: 75% L1 -> ~40%).
__global__ void __launch_bounds__(128) k_xt(const float* __restrict__ x,
                                            const float* __restrict__ W,
                                            const float* __restrict__ b) {
    __shared__ uint32_t Ws[CH * WSTRIDE];        // tf32 bits, [n][k] stride 68
    __shared__ float bs[CH];
    __shared__ uint32_t As[4][16 * WSTRIDE];     // per-warp A tile, tf32 bits
    for (int i = threadIdx.x; i < CH * CH; i += 128) {
        int k = i >> 6, n = i & 63;
        Ws[n * WSTRIDE + k] = tf32r(W[i]);
    }
    if (threadIdx.x < CH) bs[threadIdx.x] = b[threadIdx.x];
    __syncthreads();

    int lane = threadIdx.x & 31;
    int wid = threadIdx.x >> 5;
    int tile = blockIdx.x * 4 + wid;
    if (tile >= N_TILES) return;
    int row0 = tile * 16;

    // stage: 16 rows x 64 floats = 256 float4, coalesced, convert to tf32
    const float* xbase = x + (long)row0 * CH;
#pragma unroll
    for (int i = 0; i < 8; i++) {
        int idx = i * 32 + lane;
        int r = idx >> 4, c4 = (idx & 15) * 4;
        float4 v = *(const float4*)(xbase + r * CH + c4);
        *(uint4*)&As[wid][r * WSTRIDE + c4] =
            make_uint4(tf32r(v.x), tf32r(v.y), tf32r(v.z), tf32r(v.w));
    }
    __syncwarp();

    int g = lane >> 2, t = lane & 3;
    float c[8][4];
#pragma unroll
    for (int nt = 0; nt < 8; nt++) {
        float b0 = bs[nt * 8 + t * 2], b1 = bs[nt * 8 + t * 2 + 1];
        c[nt][0] = b0; c[nt][1] = b1; c[nt][2] = b0; c[nt][3] = b1;
    }
#pragma unroll
    for (int kt = 0; kt < 8; kt++) {
        uint32_t a0 = As[wid][g * WSTRIDE + kt * 8 + t];
        uint32_t a1 = As[wid][(g + 8) * WSTRIDE + kt * 8 + t];
        uint32_t a2 = As[wid][g * WSTRIDE + kt * 8 + t + 4];
        uint32_t a3 = As[wid][(g + 8) * WSTRIDE + kt * 8 + t + 4];
#pragma unroll
        for (int nt = 0; nt < 8; nt++) {
            uint32_t b0 = Ws[(nt * 8 + g) * WSTRIDE + kt * 8 + t];
            uint32_t b1 = Ws[(nt * 8 + g) * WSTRIDE + kt * 8 + t + 4];
            mma_tf32(c[nt], a0, a1, a2, a3, b0, b1);
        }
    }
#pragma unroll
    for (int nt = 0; nt < 8; nt++) {
        g_xt_h[(long)(row0 + g) * 32 + nt * 4 + t]     = f2_to_bf(c[nt][0], c[nt][1]);
        g_xt_h[(long)(row0 + g + 8) * 32 + nt * 4 + t] = f2_to_bf(c[nt][2], c[nt][3]);
    }
}

// ---------------- k_edge: m_e = binv * sum_{v in e} xt_v (bf16 gather, L2-resident) ----------------
__global__ void __launch_bounds__(256) k_edge() {
    int lane = threadIdx.x & 31;
    int e = blockIdx.x * 8 + (threadIdx.x >> 5);   // grid exact: N_HEDGES/8

    int beg = g_colptr[e], end = g_colptr[e + 1];
    float2 acc = make_float2(0.f, 0.f);
    for (int chunk = beg; chunk < end; chunk += 32) {
        int n = min(32, end - chunk);
        int idx = (lane < n) ? g_csrE[chunk + lane] : 0;
        for (int k = 0; k < n; k++) {
            int v = __shfl_sync(FULLM, idx, k);
            float2 f = bf_to_f2(g_xt_h[(long)v * 32 + lane]);
            acc.x += f.x;
            acc.y += f.y;
        }
    }
    int deg = end - beg;
    float bi = deg > 0 ? 1.f / (float)deg : 0.f;
    g_m_h[(long)e * 32 + lane] = f2_to_bf(acc.x * bi, acc.y * bi);
}

// ---------------- k_node: gather m_h -> relu -> mma with W2 -> bf16 store ----------------
// 128 threads (4 warps). warp = 16 nodes.
__global__ void __launch_bounds__(128) k_node(const float* __restrict__ W,
                                              const float* __restrict__ b) {
    __shared__ uint32_t Ws[CH * WSTRIDE];        // tf32 bits, [n][k] stride 68
    __shared__ float bs[CH];
    __shared__ uint32_t As[4][16 * WSTRIDE];     // per-warp A tile, tf32 bits
    for (int i = threadIdx.x; i < CH * CH; i += 128) {
        int k = i >> 6, n = i & 63;
        Ws[n * WSTRIDE + k] = tf32r(W[i]);
    }
    if (threadIdx.x < CH) bs[threadIdx.x] = b[threadIdx.x];
    __syncthreads();

    int lane = threadIdx.x & 31;
    int wid = threadIdx.x >> 5;
    int tile = blockIdx.x * 4 + wid;
    if (tile >= N_TILES) return;
    int row0 = tile * 16;

    // gather phase: whole warp per node; lane owns channels (2*lane, 2*lane+1)
    for (int n = 0; n < 16; n++) {
        int v = row0 + n;
        int beg = g_rowptr[v], deg = g_rowptr[v + 1] - beg;
        float2 acc = make_float2(0.f, 0.f);
        for (int j = 0; j < deg; j++) {
            int e = g_csr[beg + j];          // broadcast load (same addr all lanes)
            float2 f = bf_to_f2(g_m_h[(long)e * 32 + lane]);
            acc.x += f.x;
            acc.y += f.y;
        }
        float di = deg > 0 ? 1.f / (float)deg : 0.f;
        uint32_t h0 = tf32r(fmaxf(acc.x * di, 0.f));
        uint32_t h1 = tf32r(fmaxf(acc.y * di, 0.f));
        *(uint2*)&As[wid][n * WSTRIDE + 2 * lane] = make_uint2(h0, h1);
    }
    __syncwarp();

    // mma phase
    int g = lane >> 2, t = lane & 3;
    float c[8][4];
#pragma unroll
    for (int nt = 0; nt < 8; nt++) {
        float b0 = bs[nt * 8 + t * 2], b1 = bs[nt * 8 + t * 2 + 1];
        c[nt][0] = b0; c[nt][1] = b1; c[nt][2] = b0; c[nt][3] = b1;
    }
#pragma unroll
    for (int kt = 0; kt < 8; kt++) {
        uint32_t a0 = As[wid][g * WSTRIDE + kt * 8 + t];
        uint32_t a1 = As[wid][(g + 8) * WSTRIDE + kt * 8 + t];
        uint32_t a2 = As[wid][g * WSTRIDE + kt * 8 + t + 4];
        uint32_t a3 = As[wid][(g + 8) * WSTRIDE + kt * 8 + t + 4];
#pragma unroll
        for (int nt = 0; nt < 8; nt++) {
            uint32_t b0 = Ws[(nt * 8 + g) * WSTRIDE + kt * 8 + t];
            uint32_t b1 = Ws[(nt * 8 + g) * WSTRIDE + kt * 8 + t + 4];
            mma_tf32(c[nt], a0, a1, a2, a3, b0, b1);
        }
    }
#pragma unroll
    for (int nt = 0; nt < 8; nt++) {
        g_xt_h[(long)(row0 + g) * 32 + nt * 4 + t]     = f2_to_bf(c[nt][0], c[nt][1]);
        g_xt_h[(long)(row0 + g + 8) * 32 + nt * 4 + t] = f2_to_bf(c[nt][2], c[nt][3]);
    }
}

// ---------------- conv2 pass B + pooling + fc dot ----------------
__global__ void __launch_bounds__(256) k_conv_c(const int* __restrict__ batch,
                                                const float* __restrict__ Wfc) {
    int lane = threadIdx.x & 31;
    int warp = blockIdx.x * 8 + (threadIdx.x >> 5);
    int base = warp * 4;
    int grp = lane >> 4, c4 = (lane & 15) * 4;
    float4 wf = *(const float4*)(Wfc + c4);

    float acc = 0.f;
    int curg = -1;
#pragma unroll
    for (int n = 0; n < 4; n++) {
        int v = base + n;
        int beg = g_rowptr[v], deg = g_rowptr[v + 1] - beg;
        float4 s = make_float4(0.f, 0.f, 0.f, 0.f);
        for (int j = grp; j < deg; j += 2) {
            int e = g_csr[beg + j];
            uint2 pw = *(const uint2*)(g_m_h + (long)e * 32 + (c4 >> 1));
            float2 lo = bf_to_f2(pw.x), hi = bf_to_f2(pw.y);
            s.x += lo.x; s.y += lo.y; s.z += hi.x; s.w += hi.y;
        }
        s.x += __shfl_xor_sync(FULLM, s.x, 16);
        s.y += __shfl_xor_sync(FULLM, s.y, 16);
        s.z += __shfl_xor_sync(FULLM, s.z, 16);
        s.w += __shfl_xor_sync(FULLM, s.w, 16);
        float di = deg > 0 ? 1.f / (float)deg : 0.f;
        float p = 0.f;
        if (grp == 0) {
            p = fmaxf(di * s.x, 0.f) * wf.x + fmaxf(di * s.y, 0.f) * wf.y +
                fmaxf(di * s.z, 0.f) * wf.z + fmaxf(di * s.w, 0.f) * wf.w;
        }
#pragma unroll
        for (int o = 16; o > 0; o >>= 1) p += __shfl_xor_sync(FULLM, p, o);
        if (lane == 0) {
            int g = batch[v];
            if (g != curg) {
                if (curg >= 0) atomicAdd(&g_gsum[curg], acc);
                curg = g;
                acc = 0.f;
            }
            acc += p;
        }
    }
    if (lane == 0 && curg >= 0) atomicAdd(&g_gsum[curg], acc);
}

// ---------------- finalize ----------------
__global__ void k_fin(float* __restrict__ out, const float* __restrict__ bfc) {
    int g = blockIdx.x * blockDim.x + threadIdx.x;
    if (g < N_GRAPHS) {
        float cnt = fmaxf((float)g_gcnt[g], 1.f);
        out[g] = g_gsum[g] / cnt + bfc[0];
    }
}

// ---------------- launch ----------------
extern "C" void kernel_launch(void* const* d_in, const int* in_sizes, int n_in,
                              void* d_out, int out_size) {
    const float* x     = (const float*)d_in[0];
    const int*   eidx  = (const int*)d_in[1];
    const int*   row   = eidx;
    const int*   col   = eidx + N_INC;
    const int*   batch = (const int*)d_in[2];
    const float* W1    = (const float*)d_in[3];
    const float* b1    = (const float*)d_in[4];
    const float* W2    = (const float*)d_in[5];
    const float* b2    = (const float*)d_in[6];
    const float* Wfc   = (const float*)d_in[7];
    const float* bfc   = (const float*)d_in[8];
    float*       out   = (float*)d_out;

    const int NB_INC   = (N_INC + 255) / 256;          // 7813
    const int NB_SCANN = (N_NODES + 1023) / 1024;      // 489
    const int NB_SCANE = (N_HEDGES + 1023) / 1024;     // 98
    const int NB_MM    = (N_TILES + 3) / 4;            // 7813 (4 warps/block)
    const int NB_EDGE  = N_HEDGES / 8;                 // 12500
    const int NB_CONVC = (N_NODES / 4) / 8;            // 15625

    k_zero<<<512, 256>>>();
    k_hist<<<NB_INC, 256>>>(row, col, batch);
    k_scan1<<<NB_SCANN, 1024>>>(0);
    k_xt<<<NB_MM, 128>>>(x, W1, b1);     // position 4 -> gets the ncu capture
    k_scan2<<<1, 512>>>(0, NB_SCANN);
    k_scan3<<<NB_SCANN, 1024>>>(0);
    k_scan1<<<NB_SCANE, 1024>>>(1);
    k_scan2<<<1, 512>>>(1, NB_SCANE);
    k_scan3<<<NB_SCANE, 1024>>>(1);
    k_fill<<<NB_INC, 256>>>(row, col);
    k_edge<<<NB_EDGE, 256>>>();
    k_node<<<NB_MM, 128>>>(W2, b2);
    k_edge<<<NB_EDGE, 256>>>();
    k_conv_c<<<NB_CONVC, 256>>>(batch, Wfc);
    k_fin<<<2, 256>>>(out, bfc);
}

// round 9
// speedup vs baseline: 1.3986x; 1.0243x over previous
#include <cuda_runtime.h>
#include <cuda_bf16.h>
#include <cstdint>

#define N_NODES     500000
#define N_INC       2000000
#define N_HEDGES    100000
#define N_GRAPHS    512
#define CH          64
#define FULLM       0xffffffffu
#define N_TILES     31250          // N_NODES / 16 (even)
#define WSTRIDE     68             // padded smem row stride (conflict-free)
#define NB_SCANN    489            // ceil(N_NODES/1024)
#define NB_SCANE    98             // ceil(N_HEDGES/1024)

// ---------------- scratch (device globals; no allocation allowed) ----------------
__device__ __align__(256) uint32_t g_xt_h[(long)N_NODES * 32];   // 64 MB bf16 rows (128B each)
__device__ __align__(256) uint32_t g_m_h [(long)N_HEDGES * 32];  // 12.8 MB bf16 rows
__device__ int   g_degN[N_NODES];
__device__ int   g_degE[N_HEDGES];
__device__ int   g_rowptr[N_NODES + 1];     // node -> edges
__device__ int   g_colptr[N_HEDGES + 1];    // edge -> nodes
__device__ int   g_cursor[N_NODES];
__device__ int   g_cursorE[N_HEDGES];
__device__ int   g_csr[N_INC];              // edge ids, grouped by node
__device__ int   g_csrE[N_INC];             // node ids, grouped by edge
__device__ int   g_bsums[512];
__device__ int   g_bsumsE[512];
__device__ float g_gsum[N_GRAPHS];
__device__ int   g_gcnt[N_GRAPHS];

// ---------------- small helpers ----------------
__device__ __forceinline__ uint32_t f2_to_bf(float a, float b) {
    uint32_t r;
    asm("cvt.rn.bf16x2.f32 %0, %1, %2;" : "=r"(r) : "f"(b), "f"(a));
    return r;
}
__device__ __forceinline__ float2 bf_to_f2(uint32_t p) {
    return __bfloat1622float2(*reinterpret_cast<const __nv_bfloat162*>(&p));
}
__device__ __forceinline__ uint32_t tf32r(float f) {
    uint32_t r;
    asm("cvt.rna.tf32.f32 %0, %1;" : "=r"(r) : "f"(f));
    return r;
}
__device__ __forceinline__ void mma_tf32(float c[4],
                                         uint32_t a0, uint32_t a1, uint32_t a2, uint32_t a3,
                                         uint32_t b0, uint32_t b1) {
    asm volatile("mma.sync.aligned.m16n8k8.row.col.f32.tf32.tf32.f32 "
                 "{%0,%1,%2,%3}, {%4,%5,%6,%7}, {%8,%9}, {%0,%1,%2,%3};"
                 : "+f"(c[0]), "+f"(c[1]), "+f"(c[2]), "+f"(c[3])
                 : "r"(a0), "r"(a1), "r"(a2), "r"(a3), "r"(b0), "r"(b1));
}

// ---------------- zero scratch ----------------
__global__ void k_zero() {
    int t = blockIdx.x * blockDim.x + threadIdx.x;
    int S = gridDim.x * blockDim.x;
    for (int j = t; j < N_NODES; j += S) { g_degN[j] = 0; g_cursor[j] = 0; }
    for (int j = t; j < N_HEDGES; j += S) { g_degE[j] = 0; g_cursorE[j] = 0; }
    for (int j = t; j < N_GRAPHS; j += S) { g_gsum[j] = 0.f; g_gcnt[j] = 0; }
}

// ---------------- degree histograms + graph-size histogram ----------------
__global__ void k_hist(const int* __restrict__ row, const int* __restrict__ col,
                       const int* __restrict__ batch) {
    int i = blockIdx.x * blockDim.x + threadIdx.x;
    if (i < N_INC) {
        atomicAdd(&g_degN[row[i]], 1);
        atomicAdd(&g_degE[col[i]], 1);
    }
    unsigned act = __ballot_sync(FULLM, i < N_NODES);
    if (i < N_NODES) {
        int g = batch[i];
        unsigned mask = __match_any_sync(act, g);
        int leader = __ffs(mask) - 1;
        if ((threadIdx.x & 31) == leader) atomicAdd(&g_gcnt[g], __popc(mask));
    }
}

// ---------------- merged exclusive scans (node blocks first, then edge blocks) ----------------
__global__ void k_scan1m() {
    int mode = blockIdx.x >= NB_SCANN;
    int blk = mode ? blockIdx.x - NB_SCANN : blockIdx.x;
    const int* __restrict__ in = mode ? g_degE : g_degN;
    int* __restrict__ out = mode ? g_colptr : g_rowptr;
    int* __restrict__ bsum = mode ? g_bsumsE : g_bsums;
    int n = mode ? N_HEDGES : N_NODES;
    __shared__ int sh[1024];
    int tid = threadIdx.x;
    int i = blk * 1024 + tid;
    int v = (i < n) ? in[i] : 0;
    sh[tid] = v;
    __syncthreads();
#pragma unroll
    for (int off = 1; off < 1024; off <<= 1) {
        int t = (tid >= off) ? sh[tid - off] : 0;
        __syncthreads();
        sh[tid] += t;
        __syncthreads();
    }
    if (i < n) out[i] = sh[tid] - v;
    if (tid == 1023) bsum[blk] = sh[1023];
}

__global__ void k_scan2m() {
    __shared__ int sh[512];
    int tid = threadIdx.x;
#pragma unroll
    for (int mode = 0; mode < 2; mode++) {
        int* __restrict__ bsum = mode ? g_bsumsE : g_bsums;
        int nblocks = mode ? NB_SCANE : NB_SCANN;
        int v = (tid < nblocks) ? bsum[tid] : 0;
        sh[tid] = v;
        __syncthreads();
#pragma unroll
        for (int off = 1; off < 512; off <<= 1) {
            int t = (tid >= off) ? sh[tid - off] : 0;
            __syncthreads();
            sh[tid] += t;
            __syncthreads();
        }
        if (tid < nblocks) bsum[tid] = sh[tid] - v;
        __syncthreads();
    }
}

__global__ void k_scan3m() {
    int mode = blockIdx.x >= NB_SCANN;
    int blk = mode ? blockIdx.x - NB_SCANN : blockIdx.x;
    int* __restrict__ out = mode ? g_colptr : g_rowptr;
    const int* __restrict__ bsum = mode ? g_bsumsE : g_bsums;
    int n = mode ? N_HEDGES : N_NODES;
    int i = blk * 1024 + threadIdx.x;
    if (i < n) out[i] += bsum[blk];
    if (i == 0) out[n] = N_INC;
}

// ---------------- fill both CSRs ----------------
__global__ void k_fill(const int* __restrict__ row, const int* __restrict__ col) {
    int i = blockIdx.x * blockDim.x + threadIdx.x;
    if (i < N_INC) {
        int r = row[i], c = col[i];
        int pr = g_rowptr[r] + atomicAdd(&g_cursor[r], 1);
        g_csr[pr] = c;
        int pc = g_colptr[c] + atomicAdd(&g_cursorE[c], 1);
        g_csrE[pc] = r;
    }
}

// ---------------- k_xt: xt = x W1 + b1 via tf32 mma ----------------
// 128 threads / 4 warps; warp = 2 tiles of 16 nodes. kt-outer loop keeps the 16
// B-fragment regs loaded once per kt and reuses them for both tiles -> B LDS
// wavefronts per tile halved (the dominant L1 client at 77.8% L1).
// Dynamic smem: Ws[64*68] + per-warp A[32*68]  (51 KB).
extern __shared__ uint32_t xt_smem[];
__global__ void __launch_bounds__(128) k_xt(const float* __restrict__ x,
                                            const float* __restrict__ W,
                                            const float* __restrict__ b) {
    uint32_t* Ws = xt_smem;                       // tf32 bits, [n][k] stride 68
    __shared__ float bs[CH];
    for (int i = threadIdx.x; i < CH * CH; i += 128) {
        int k = i >> 6, n = i & 63;
        Ws[n * WSTRIDE + k] = tf32r(W[i]);
    }
    if (threadIdx.x < CH) bs[threadIdx.x] = b[threadIdx.x];
    __syncthreads();

    int lane = threadIdx.x & 31;
    int wid = threadIdx.x >> 5;
    int wg = blockIdx.x * 4 + wid;
    int tileBase = wg * 2;
    if (tileBase >= N_TILES) return;   // N_TILES even -> both tiles valid
    int row0 = tileBase * 16;
    uint32_t* myA = xt_smem + CH * WSTRIDE + wid * (32 * WSTRIDE);

    // stage 32 rows x 64 floats, coalesced float4, convert to tf32
    const float* xbase = x + (long)row0 * CH;
#pragma unroll
    for (int i = 0; i < 16; i++) {
        int idx = i * 32 + lane;
        int r = idx >> 4, c4 = (idx & 15) * 4;
        float4 v = *(const float4*)(xbase + r * CH + c4);
        *(uint4*)&myA[r * WSTRIDE + c4] =
            make_uint4(tf32r(v.x), tf32r(v.y), tf32r(v.z), tf32r(v.w));
    }
    __syncwarp();

    int g = lane >> 2, t = lane & 3;
    float c[2][8][4];
#pragma unroll
    for (int tt = 0; tt < 2; tt++)
#pragma unroll
        for (int nt = 0; nt < 8; nt++) {
            float b0 = bs[nt * 8 + t * 2], b1 = bs[nt * 8 + t * 2 + 1];
            c[tt][nt][0] = b0; c[tt][nt][1] = b1; c[tt][nt][2] = b0; c[tt][nt][3] = b1;
        }

#pragma unroll
    for (int kt = 0; kt < 8; kt++) {
        uint32_t B0[8], B1[8];
#pragma unroll
        for (int nt = 0; nt < 8; nt++) {
            B0[nt] = Ws[(nt * 8 + g) * WSTRIDE + kt * 8 + t];
            B1[nt] = Ws[(nt * 8 + g) * WSTRIDE + kt * 8 + t + 4];
        }
#pragma unroll
        for (int tt = 0; tt < 2; tt++) {
            int rb = tt * 16;
            uint32_t a0 = myA[(rb + g) * WSTRIDE + kt * 8 + t];
            uint32_t a1 = myA[(rb + g + 8) * WSTRIDE + kt * 8 + t];
            uint32_t a2 = myA[(rb + g) * WSTRIDE + kt * 8 + t + 4];
            uint32_t a3 = myA[(rb + g + 8) * WSTRIDE + kt * 8 + t + 4];
#pragma unroll
            for (int nt = 0; nt < 8; nt++)
                mma_tf32(c[tt][nt], a0, a1, a2, a3, B0[nt], B1[nt]);
        }
    }

#pragma unroll
    for (int tt = 0; tt < 2; tt++) {
        int r0 = row0 + tt * 16;
#pragma unroll
        for (int nt = 0; nt < 8; nt++) {
            g_xt_h[(long)(r0 + g) * 32 + nt * 4 + t]     = f2_to_bf(c[tt][nt][0], c[tt][nt][1]);
            g_xt_h[(long)(r0 + g + 8) * 32 + nt * 4 + t] = f2_to_bf(c[tt][nt][2], c[tt][nt][3]);
        }
    }
}

// ---------------- k_edge: m_e = binv * sum_{v in e} xt_v (bf16 gather, L2-resident) ----------------
__global__ void __launch_bounds__(256) k_edge() {
    int lane = threadIdx.x & 31;
    int e = blockIdx.x * 8 + (threadIdx.x >> 5);   // grid exact: N_HEDGES/8

    int beg = g_colptr[e], end = g_colptr[e + 1];
    float2 acc = make_float2(0.f, 0.f);
    for (int chunk = beg; chunk < end; chunk += 32) {
        int n = min(32, end - chunk);
        int idx = (lane < n) ? g_csrE[chunk + lane] : 0;
        for (int k = 0; k < n; k++) {
            int v = __shfl_sync(FULLM, idx, k);
            float2 f = bf_to_f2(g_xt_h[(long)v * 32 + lane]);
            acc.x += f.x;
            acc.y += f.y;
        }
    }
    int deg = end - beg;
    float bi = deg > 0 ? 1.f / (float)deg : 0.f;
    g_m_h[(long)e * 32 + lane] = f2_to_bf(acc.x * bi, acc.y * bi);
}

// ---------------- k_node: gather m_h -> relu -> mma with W2 -> bf16 store ----------------
// 128 threads (4 warps). warp = 16 nodes.
__global__ void __launch_bounds__(128) k_node(const float* __restrict__ W,
                                              const float* __restrict__ b) {
    __shared__ uint32_t Ws[CH * WSTRIDE];        // tf32 bits, [n][k] stride 68
    __shared__ float bs[CH];
    __shared__ uint32_t As[4][16 * WSTRIDE];     // per-warp A tile, tf32 bits
    for (int i = threadIdx.x; i < CH * CH; i += 128) {
        int k = i >> 6, n = i & 63;
        Ws[n * WSTRIDE + k] = tf32r(W[i]);
    }
    if (threadIdx.x < CH) bs[threadIdx.x] = b[threadIdx.x];
    __syncthreads();

    int lane = threadIdx.x & 31;
    int wid = threadIdx.x >> 5;
    int tile = blockIdx.x * 4 + wid;
    if (tile >= N_TILES) return;
    int row0 = tile * 16;

    // gather phase: whole warp per node; lane owns channels (2*lane, 2*lane+1)
    for (int n = 0; n < 16; n++) {
        int v = row0 + n;
        int beg = g_rowptr[v], deg = g_rowptr[v + 1] - beg;
        float2 acc = make_float2(0.f, 0.f);
        for (int j = 0; j < deg; j++) {
            int e = g_csr[beg + j];          // broadcast load (same addr all lanes)
            float2 f = bf_to_f2(g_m_h[(long)e * 32 + lane]);
            acc.x += f.x;
            acc.y += f.y;
        }
        float di = deg > 0 ? 1.f / (float)deg : 0.f;
        uint32_t h0 = tf32r(fmaxf(acc.x * di, 0.f));
        uint32_t h1 = tf32r(fmaxf(acc.y * di, 0.f));
        *(uint2*)&As[wid][n * WSTRIDE + 2 * lane] = make_uint2(h0, h1);
    }
    __syncwarp();

    // mma phase
    int g = lane >> 2, t = lane & 3;
    float c[8][4];
#pragma unroll
    for (int nt = 0; nt < 8; nt++) {
        float b0 = bs[nt * 8 + t * 2], b1 = bs[nt * 8 + t * 2 + 1];
        c[nt][0] = b0; c[nt][1] = b1; c[nt][2] = b0; c[nt][3] = b1;
    }
#pragma unroll
    for (int kt = 0; kt < 8; kt++) {
        uint32_t a0 = As[wid][g * WSTRIDE + kt * 8 + t];
        uint32_t a1 = As[wid][(g + 8) * WSTRIDE + kt * 8 + t];
        uint32_t a2 = As[wid][g * WSTRIDE + kt * 8 + t + 4];
        uint32_t a3 = As[wid][(g + 8) * WSTRIDE + kt * 8 + t + 4];
#pragma unroll
        for (int nt = 0; nt < 8; nt++) {
            uint32_t b0 = Ws[(nt * 8 + g) * WSTRIDE + kt * 8 + t];
            uint32_t b1 = Ws[(nt * 8 + g) * WSTRIDE + kt * 8 + t + 4];
            mma_tf32(c[nt], a0, a1, a2, a3, b0, b1);
        }
    }
#pragma unroll
    for (int nt = 0; nt < 8; nt++) {
        g_xt_h[(long)(row0 + g) * 32 + nt * 4 + t]     = f2_to_bf(c[nt][0], c[nt][1]);
        g_xt_h[(long)(row0 + g + 8) * 32 + nt * 4 + t] = f2_to_bf(c[nt][2], c[nt][3]);
    }
}

// ---------------- conv2 pass B + pooling + fc dot ----------------
__global__ void __launch_bounds__(256) k_conv_c(const int* __restrict__ batch,
                                                const float* __restrict__ Wfc) {
    int lane = threadIdx.x & 31;
    int warp = blockIdx.x * 8 + (threadIdx.x >> 5);
    int base = warp * 4;
    int grp = lane >> 4, c4 = (lane & 15) * 4;
    float4 wf = *(const float4*)(Wfc + c4);

    float acc = 0.f;
    int curg = -1;
#pragma unroll
    for (int n = 0; n < 4; n++) {
        int v = base + n;
        int beg = g_rowptr[v], deg = g_rowptr[v + 1] - beg;
        float4 s = make_float4(0.f, 0.f, 0.f, 0.f);
        for (int j = grp; j < deg; j += 2) {
            int e = g_csr[beg + j];
            uint2 pw = *(const uint2*)(g_m_h + (long)e * 32 + (c4 >> 1));
            float2 lo = bf_to_f2(pw.x), hi = bf_to_f2(pw.y);
            s.x += lo.x; s.y += lo.y; s.z += hi.x; s.w += hi.y;
        }
        s.x += __shfl_xor_sync(FULLM, s.x, 16);
        s.y += __shfl_xor_sync(FULLM, s.y, 16);
        s.z += __shfl_xor_sync(FULLM, s.z, 16);
        s.w += __shfl_xor_sync(FULLM, s.w, 16);
        float di = deg > 0 ? 1.f / (float)deg : 0.f;
        float p = 0.f;
        if (grp == 0) {
            p = fmaxf(di * s.x, 0.f) * wf.x + fmaxf(di * s.y, 0.f) * wf.y +
                fmaxf(di * s.z, 0.f) * wf.z + fmaxf(di * s.w, 0.f) * wf.w;
        }
#pragma unroll
        for (int o = 16; o > 0; o >>= 1) p += __shfl_xor_sync(FULLM, p, o);
        if (lane == 0) {
            int g = batch[v];
            if (g != curg) {
                if (curg >= 0) atomicAdd(&g_gsum[curg], acc);
                curg = g;
                acc = 0.f;
            }
            acc += p;
        }
    }
    if (lane == 0 && curg >= 0) atomicAdd(&g_gsum[curg], acc);
}

// ---------------- finalize ----------------
__global__ void k_fin(float* __restrict__ out, const float* __restrict__ bfc) {
    int g = blockIdx.x * blockDim.x + threadIdx.x;
    if (g < N_GRAPHS) {
        float cnt = fmaxf((float)g_gcnt[g], 1.f);
        out[g] = g_gsum[g] / cnt + bfc[0];
    }
}

// ---------------- launch ----------------
extern "C" void kernel_launch(void* const* d_in, const int* in_sizes, int n_in,
                              void* d_out, int out_size) {
    const float* x     = (const float*)d_in[0];
    const int*   eidx  = (const int*)d_in[1];
    const int*   row   = eidx;
    const int*   col   = eidx + N_INC;
    const int*   batch = (const int*)d_in[2];
    const float* W1    = (const float*)d_in[3];
    const float* b1    = (const float*)d_in[4];
    const float* W2    = (const float*)d_in[5];
    const float* b2    = (const float*)d_in[6];
    const float* Wfc   = (const float*)d_in[7];
    const float* bfc   = (const float*)d_in[8];
    float*       out   = (float*)d_out;

    const int XT_SMEM  = (CH * WSTRIDE + 4 * 32 * WSTRIDE) * 4;   // 52224 B
    static bool attr_done = false;
    if (!attr_done) {
        cudaFuncSetAttribute(k_xt, cudaFuncAttributeMaxDynamicSharedMemorySize, XT_SMEM);
        attr_done = true;
    }

    const int NB_INC   = (N_INC + 255) / 256;          // 7813
    const int NB_XT    = (N_TILES / 2 + 3) / 4;        // 3907 (4 warps x 2 tiles)
    const int NB_MM    = (N_TILES + 3) / 4;            // 7813
    const int NB_EDGE  = N_HEDGES / 8;                 // 12500
    const int NB_CONVC = (N_NODES / 4) / 8;            // 15625

    k_zero<<<512, 256>>>();
    k_hist<<<NB_INC, 256>>>(row, col, batch);
    k_scan1m<<<NB_SCANN + NB_SCANE, 1024>>>();
    k_xt<<<NB_XT, 128, XT_SMEM>>>(x, W1, b1);   // position 4 -> gets the ncu capture
    k_scan2m<<<1, 512>>>();
    k_scan3m<<<NB_SCANN + NB_SCANE, 1024>>>();
    k_fill<<<NB_INC, 256>>>(row, col);
    k_edge<<<NB_EDGE, 256>>>();
    k_node<<<NB_MM, 128>>>(W2, b2);
    k_edge<<<NB_EDGE, 256>>>();
    k_conv_c<<<NB_CONVC, 256>>>(batch, Wfc);
    k_fin<<<2, 256>>>(out, bfc);
}

// round 10
// speedup vs baseline: 1.4408x; 1.0302x over previous
#include <cuda_runtime.h>
#include <cuda_bf16.h>
#include <cstdint>

#define N_NODES     500000
#define N_INC       2000000
#define N_HEDGES    100000
#define N_GRAPHS    512
#define CH          64
#define FULLM       0xffffffffu
#define N_TILES     31250          // N_NODES / 16 (even)
#define WSTRIDE     68             // padded smem row stride for A/W tiles
#define CSTRIDE     36             // C-stage stride: bank=(4r+c)%32 conflict-free
#define NB_SCANN    489            // ceil(N_NODES/1024)
#define NB_SCANE    98             // ceil(N_HEDGES/1024)

// ---------------- scratch (device globals; no allocation allowed) ----------------
__device__ __align__(256) uint32_t g_xt_h[(long)N_NODES * 32];   // 64 MB bf16 rows (128B each)
__device__ __align__(256) uint32_t g_m_h [(long)N_HEDGES * 32];  // 12.8 MB bf16 rows
__device__ int   g_degN[N_NODES];
__device__ int   g_degE[N_HEDGES];
__device__ int   g_rowptr[N_NODES + 1];     // node -> edges
__device__ int   g_colptr[N_HEDGES + 1];    // edge -> nodes
__device__ int   g_cursor[N_NODES];
__device__ int   g_cursorE[N_HEDGES];
__device__ int   g_csr[N_INC];              // edge ids, grouped by node
__device__ int   g_csrE[N_INC];             // node ids, grouped by edge
__device__ int   g_bsums[512];
__device__ int   g_bsumsE[512];
__device__ float g_gsum[N_GRAPHS];
__device__ int   g_gcnt[N_GRAPHS];

// ---------------- small helpers ----------------
__device__ __forceinline__ uint32_t f2_to_bf(float a, float b) {
    uint32_t r;
    asm("cvt.rn.bf16x2.f32 %0, %1, %2;" : "=r"(r) : "f"(b), "f"(a));
    return r;
}
__device__ __forceinline__ float2 bf_to_f2(uint32_t p) {
    return __bfloat1622float2(*reinterpret_cast<const __nv_bfloat162*>(&p));
}
__device__ __forceinline__ uint32_t tf32r(float f) {
    uint32_t r;
    asm("cvt.rna.tf32.f32 %0, %1;" : "=r"(r) : "f"(f));
    return r;
}
__device__ __forceinline__ void mma_tf32(float c[4],
                                         uint32_t a0, uint32_t a1, uint32_t a2, uint32_t a3,
                                         uint32_t b0, uint32_t b1) {
    asm volatile("mma.sync.aligned.m16n8k8.row.col.f32.tf32.tf32.f32 "
                 "{%0,%1,%2,%3}, {%4,%5,%6,%7}, {%8,%9}, {%0,%1,%2,%3};"
                 : "+f"(c[0]), "+f"(c[1]), "+f"(c[2]), "+f"(c[3])
                 : "r"(a0), "r"(a1), "r"(a2), "r"(a3), "r"(b0), "r"(b1));
}

// ---------------- zero scratch ----------------
__global__ void k_zero() {
    int t = blockIdx.x * blockDim.x + threadIdx.x;
    int S = gridDim.x * blockDim.x;
    for (int j = t; j < N_NODES; j += S) { g_degN[j] = 0; g_cursor[j] = 0; }
    for (int j = t; j < N_HEDGES; j += S) { g_degE[j] = 0; g_cursorE[j] = 0; }
    for (int j = t; j < N_GRAPHS; j += S) { g_gsum[j] = 0.f; g_gcnt[j] = 0; }
}

// ---------------- degree histograms + graph-size histogram ----------------
__global__ void k_hist(const int* __restrict__ row, const int* __restrict__ col,
                       const int* __restrict__ batch) {
    int i = blockIdx.x * blockDim.x + threadIdx.x;
    if (i < N_INC) {
        atomicAdd(&g_degN[row[i]], 1);
        atomicAdd(&g_degE[col[i]], 1);
    }
    unsigned act = __ballot_sync(FULLM, i < N_NODES);
    if (i < N_NODES) {
        int g = batch[i];
        unsigned mask = __match_any_sync(act, g);
        int leader = __ffs(mask) - 1;
        if ((threadIdx.x & 31) == leader) atomicAdd(&g_gcnt[g], __popc(mask));
    }
}

// ---------------- merged exclusive scans (node blocks first, then edge blocks) ----------------
__global__ void k_scan1m() {
    int mode = blockIdx.x >= NB_SCANN;
    int blk = mode ? blockIdx.x - NB_SCANN : blockIdx.x;
    const int* __restrict__ in = mode ? g_degE : g_degN;
    int* __restrict__ out = mode ? g_colptr : g_rowptr;
    int* __restrict__ bsum = mode ? g_bsumsE : g_bsums;
    int n = mode ? N_HEDGES : N_NODES;
    __shared__ int sh[1024];
    int tid = threadIdx.x;
    int i = blk * 1024 + tid;
    int v = (i < n) ? in[i] : 0;
    sh[tid] = v;
    __syncthreads();
#pragma unroll
    for (int off = 1; off < 1024; off <<= 1) {
        int t = (tid >= off) ? sh[tid - off] : 0;
        __syncthreads();
        sh[tid] += t;
        __syncthreads();
    }
    if (i < n) out[i] = sh[tid] - v;
    if (tid == 1023) bsum[blk] = sh[1023];
}

__global__ void k_scan2m() {
    __shared__ int sh[512];
    int tid = threadIdx.x;
#pragma unroll
    for (int mode = 0; mode < 2; mode++) {
        int* __restrict__ bsum = mode ? g_bsumsE : g_bsums;
        int nblocks = mode ? NB_SCANE : NB_SCANN;
        int v = (tid < nblocks) ? bsum[tid] : 0;
        sh[tid] = v;
        __syncthreads();
#pragma unroll
        for (int off = 1; off < 512; off <<= 1) {
            int t = (tid >= off) ? sh[tid - off] : 0;
            __syncthreads();
            sh[tid] += t;
            __syncthreads();
        }
        if (tid < nblocks) bsum[tid] = sh[tid] - v;
        __syncthreads();
    }
}

__global__ void k_scan3m() {
    int mode = blockIdx.x >= NB_SCANN;
    int blk = mode ? blockIdx.x - NB_SCANN : blockIdx.x;
    int* __restrict__ out = mode ? g_colptr : g_rowptr;
    const int* __restrict__ bsum = mode ? g_bsumsE : g_bsums;
    int n = mode ? N_HEDGES : N_NODES;
    int i = blk * 1024 + threadIdx.x;
    if (i < n) out[i] += bsum[blk];
    if (i == 0) out[n] = N_INC;
}

// ---------------- fill both CSRs ----------------
__global__ void k_fill(const int* __restrict__ row, const int* __restrict__ col) {
    int i = blockIdx.x * blockDim.x + threadIdx.x;
    if (i < N_INC) {
        int r = row[i], c = col[i];
        int pr = g_rowptr[r] + atomicAdd(&g_cursor[r], 1);
        g_csr[pr] = c;
        int pc = g_colptr[c] + atomicAdd(&g_cursorE[c], 1);
        g_csrE[pc] = r;
    }
}

// ---------------- k_xt: xt = x W1 + b1 via tf32 mma ----------------
// 128 threads / 4 warps; warp = 2 tiles of 16 nodes. kt-outer B-frag reuse.
// C staged through smem (stride 36, conflict-free) -> row-coalesced STG.
extern __shared__ uint32_t xt_smem[];
__global__ void __launch_bounds__(128) k_xt(const float* __restrict__ x,
                                            const float* __restrict__ W,
                                            const float* __restrict__ b) {
    uint32_t* Ws = xt_smem;                       // tf32 bits, [n][k] stride 68
    __shared__ float bs[CH];
    for (int i = threadIdx.x; i < CH * CH; i += 128) {
        int k = i >> 6, n = i & 63;
        Ws[n * WSTRIDE + k] = tf32r(W[i]);
    }
    if (threadIdx.x < CH) bs[threadIdx.x] = b[threadIdx.x];
    __syncthreads();

    int lane = threadIdx.x & 31;
    int wid = threadIdx.x >> 5;
    int wg = blockIdx.x * 4 + wid;
    int tileBase = wg * 2;
    if (tileBase >= N_TILES) return;   // N_TILES even -> both tiles valid
    int row0 = tileBase * 16;
    uint32_t* myA = xt_smem + CH * WSTRIDE + wid * (32 * WSTRIDE);

    // stage 32 rows x 64 floats, coalesced float4, convert to tf32
    const float* xbase = x + (long)row0 * CH;
#pragma unroll
    for (int i = 0; i < 16; i++) {
        int idx = i * 32 + lane;
        int r = idx >> 4, c4 = (idx & 15) * 4;
        float4 v = *(const float4*)(xbase + r * CH + c4);
        *(uint4*)&myA[r * WSTRIDE + c4] =
            make_uint4(tf32r(v.x), tf32r(v.y), tf32r(v.z), tf32r(v.w));
    }
    __syncwarp();

    int g = lane >> 2, t = lane & 3;
    float c[2][8][4];
#pragma unroll
    for (int tt = 0; tt < 2; tt++)
#pragma unroll
        for (int nt = 0; nt < 8; nt++) {
            float b0 = bs[nt * 8 + t * 2], b1 = bs[nt * 8 + t * 2 + 1];
            c[tt][nt][0] = b0; c[tt][nt][1] = b1; c[tt][nt][2] = b0; c[tt][nt][3] = b1;
        }

#pragma unroll
    for (int kt = 0; kt < 8; kt++) {
        uint32_t B0[8], B1[8];
#pragma unroll
        for (int nt = 0; nt < 8; nt++) {
            B0[nt] = Ws[(nt * 8 + g) * WSTRIDE + kt * 8 + t];
            B1[nt] = Ws[(nt * 8 + g) * WSTRIDE + kt * 8 + t + 4];
        }
#pragma unroll
        for (int tt = 0; tt < 2; tt++) {
            int rb = tt * 16;
            uint32_t a0 = myA[(rb + g) * WSTRIDE + kt * 8 + t];
            uint32_t a1 = myA[(rb + g + 8) * WSTRIDE + kt * 8 + t];
            uint32_t a2 = myA[(rb + g) * WSTRIDE + kt * 8 + t + 4];
            uint32_t a3 = myA[(rb + g + 8) * WSTRIDE + kt * 8 + t + 4];
#pragma unroll
            for (int nt = 0; nt < 8; nt++)
                mma_tf32(c[tt][nt], a0, a1, a2, a3, B0[nt], B1[nt]);
        }
    }

    // C -> smem (stride 36) -> coalesced bf16 rows
    __syncwarp();
#pragma unroll
    for (int tt = 0; tt < 2; tt++)
#pragma unroll
        for (int nt = 0; nt < 8; nt++) {
            myA[(tt * 16 + g) * CSTRIDE + nt * 4 + t]     = f2_to_bf(c[tt][nt][0], c[tt][nt][1]);
            myA[(tt * 16 + g + 8) * CSTRIDE + nt * 4 + t] = f2_to_bf(c[tt][nt][2], c[tt][nt][3]);
        }
    __syncwarp();
#pragma unroll
    for (int r = 0; r < 32; r++)
        g_xt_h[(long)(row0 + r) * 32 + lane] = myA[r * CSTRIDE + lane];
}

// ---------------- k_edge: m_e = binv * sum_{v in e} xt_v (bf16 gather, MLP-4) ----------------
__global__ void __launch_bounds__(256) k_edge() {
    int lane = threadIdx.x & 31;
    int e = blockIdx.x * 8 + (threadIdx.x >> 5);   // grid exact: N_HEDGES/8

    int beg = g_colptr[e], end = g_colptr[e + 1];
    float2 acc = make_float2(0.f, 0.f);
    for (int chunk = beg; chunk < end; chunk += 32) {
        int n = min(32, end - chunk);
        int idx = (lane < n) ? g_csrE[chunk + lane] : 0;
        int k = 0;
        for (; k + 4 <= n; k += 4) {
            int v0 = __shfl_sync(FULLM, idx, k);
            int v1 = __shfl_sync(FULLM, idx, k + 1);
            int v2 = __shfl_sync(FULLM, idx, k + 2);
            int v3 = __shfl_sync(FULLM, idx, k + 3);
            uint32_t p0 = g_xt_h[(long)v0 * 32 + lane];
            uint32_t p1 = g_xt_h[(long)v1 * 32 + lane];
            uint32_t p2 = g_xt_h[(long)v2 * 32 + lane];
            uint32_t p3 = g_xt_h[(long)v3 * 32 + lane];
            float2 f0 = bf_to_f2(p0), f1 = bf_to_f2(p1);
            float2 f2 = bf_to_f2(p2), f3 = bf_to_f2(p3);
            acc.x += (f0.x + f1.x) + (f2.x + f3.x);
            acc.y += (f0.y + f1.y) + (f2.y + f3.y);
        }
        for (; k < n; k++) {
            int v = __shfl_sync(FULLM, idx, k);
            float2 f = bf_to_f2(g_xt_h[(long)v * 32 + lane]);
            acc.x += f.x;
            acc.y += f.y;
        }
    }
    int deg = end - beg;
    float bi = deg > 0 ? 1.f / (float)deg : 0.f;
    g_m_h[(long)e * 32 + lane] = f2_to_bf(acc.x * bi, acc.y * bi);
}

// ---------------- k_node: gather m_h (MLP-4) -> relu -> mma -> staged bf16 store ----------------
__global__ void __launch_bounds__(128) k_node(const float* __restrict__ W,
                                              const float* __restrict__ b) {
    __shared__ uint32_t Ws[CH * WSTRIDE];        // tf32 bits, [n][k] stride 68
    __shared__ float bs[CH];
    __shared__ uint32_t As[4][16 * WSTRIDE];     // per-warp A tile / later C stage
    for (int i = threadIdx.x; i < CH * CH; i += 128) {
        int k = i >> 6, n = i & 63;
        Ws[n * WSTRIDE + k] = tf32r(W[i]);
    }
    if (threadIdx.x < CH) bs[threadIdx.x] = b[threadIdx.x];
    __syncthreads();

    int lane = threadIdx.x & 31;
    int wid = threadIdx.x >> 5;
    int tile = blockIdx.x * 4 + wid;
    if (tile >= N_TILES) return;
    int row0 = tile * 16;
    uint32_t* myA = As[wid];

    // gather phase: warp per node; lane owns channels (2*lane, 2*lane+1); MLP-4
    for (int n = 0; n < 16; n++) {
        int v = row0 + n;
        int j = g_rowptr[v], end = g_rowptr[v + 1];
        int deg = end - j;
        float2 acc = make_float2(0.f, 0.f);
        for (; j + 4 <= end; j += 4) {
            int e0 = g_csr[j], e1 = g_csr[j + 1], e2 = g_csr[j + 2], e3 = g_csr[j + 3];
            uint32_t p0 = g_m_h[(long)e0 * 32 + lane];
            uint32_t p1 = g_m_h[(long)e1 * 32 + lane];
            uint32_t p2 = g_m_h[(long)e2 * 32 + lane];
            uint32_t p3 = g_m_h[(long)e3 * 32 + lane];
            float2 f0 = bf_to_f2(p0), f1 = bf_to_f2(p1);
            float2 f2 = bf_to_f2(p2), f3 = bf_to_f2(p3);
            acc.x += (f0.x + f1.x) + (f2.x + f3.x);
            acc.y += (f0.y + f1.y) + (f2.y + f3.y);
        }
        for (; j < end; j++) {
            int e = g_csr[j];
            float2 f = bf_to_f2(g_m_h[(long)e * 32 + lane]);
            acc.x += f.x;
            acc.y += f.y;
        }
        float di = deg > 0 ? 1.f / (float)deg : 0.f;
        uint32_t h0 = tf32r(fmaxf(acc.x * di, 0.f));
        uint32_t h1 = tf32r(fmaxf(acc.y * di, 0.f));
        *(uint2*)&myA[n * WSTRIDE + 2 * lane] = make_uint2(h0, h1);
    }
    __syncwarp();

    // mma phase
    int g = lane >> 2, t = lane & 3;
    float c[8][4];
#pragma unroll
    for (int nt = 0; nt < 8; nt++) {
        float b0 = bs[nt * 8 + t * 2], b1 = bs[nt * 8 + t * 2 + 1];
        c[nt][0] = b0; c[nt][1] = b1; c[nt][2] = b0; c[nt][3] = b1;
    }
#pragma unroll
    for (int kt = 0; kt < 8; kt++) {
        uint32_t a0 = myA[g * WSTRIDE + kt * 8 + t];
        uint32_t a1 = myA[(g + 8) * WSTRIDE + kt * 8 + t];
        uint32_t a2 = myA[g * WSTRIDE + kt * 8 + t + 4];
        uint32_t a3 = myA[(g + 8) * WSTRIDE + kt * 8 + t + 4];
#pragma unroll
        for (int nt = 0; nt < 8; nt++) {
            uint32_t b0 = Ws[(nt * 8 + g) * WSTRIDE + kt * 8 + t];
            uint32_t b1 = Ws[(nt * 8 + g) * WSTRIDE + kt * 8 + t + 4];
            mma_tf32(c[nt], a0, a1, a2, a3, b0, b1);
        }
    }

    // C -> smem (stride 36) -> coalesced bf16 rows
    __syncwarp();
#pragma unroll
    for (int nt = 0; nt < 8; nt++) {
        myA[g * CSTRIDE + nt * 4 + t]       = f2_to_bf(c[nt][0], c[nt][1]);
        myA[(g + 8) * CSTRIDE + nt * 4 + t] = f2_to_bf(c[nt][2], c[nt][3]);
    }
    __syncwarp();
#pragma unroll
    for (int r = 0; r < 16; r++)
        g_xt_h[(long)(row0 + r) * 32 + lane] = myA[r * CSTRIDE + lane];
}

// ---------------- conv2 pass B + pooling + fc dot (MLP-2) ----------------
__global__ void __launch_bounds__(256) k_conv_c(const int* __restrict__ batch,
                                                const float* __restrict__ Wfc) {
    int lane = threadIdx.x & 31;
    int warp = blockIdx.x * 8 + (threadIdx.x >> 5);
    int base = warp * 4;
    int grp = lane >> 4, c4 = (lane & 15) * 4;
    float4 wf = *(const float4*)(Wfc + c4);

    float acc = 0.f;
    int curg = -1;
#pragma unroll
    for (int n = 0; n < 4; n++) {
        int v = base + n;
        int beg = g_rowptr[v], deg = g_rowptr[v + 1] - beg;
        float4 s = make_float4(0.f, 0.f, 0.f, 0.f);
        int j = grp;
        for (; j + 2 < deg; j += 4) {
            int e0 = g_csr[beg + j];
            int e1 = g_csr[beg + j + 2];
            uint2 p0 = *(const uint2*)(g_m_h + (long)e0 * 32 + (c4 >> 1));
            uint2 p1 = *(const uint2*)(g_m_h + (long)e1 * 32 + (c4 >> 1));
            float2 l0 = bf_to_f2(p0.x), h0 = bf_to_f2(p0.y);
            float2 l1 = bf_to_f2(p1.x), h1 = bf_to_f2(p1.y);
            s.x += l0.x + l1.x; s.y += l0.y + l1.y;
            s.z += h0.x + h1.x; s.w += h0.y + h1.y;
        }
        if (j < deg) {
            int e = g_csr[beg + j];
            uint2 pw = *(const uint2*)(g_m_h + (long)e * 32 + (c4 >> 1));
            float2 lo = bf_to_f2(pw.x), hi = bf_to_f2(pw.y);
            s.x += lo.x; s.y += lo.y; s.z += hi.x; s.w += hi.y;
        }
        s.x += __shfl_xor_sync(FULLM, s.x, 16);
        s.y += __shfl_xor_sync(FULLM, s.y, 16);
        s.z += __shfl_xor_sync(FULLM, s.z, 16);
        s.w += __shfl_xor_sync(FULLM, s.w, 16);
        float di = deg > 0 ? 1.f / (float)deg : 0.f;
        float p = 0.f;
        if (grp == 0) {
            p = fmaxf(di * s.x, 0.f) * wf.x + fmaxf(di * s.y, 0.f) * wf.y +
                fmaxf(di * s.z, 0.f) * wf.z + fmaxf(di * s.w, 0.f) * wf.w;
        }
#pragma unroll
        for (int o = 16; o > 0; o >>= 1) p += __shfl_xor_sync(FULLM, p, o);
        if (lane == 0) {
            int g = batch[v];
            if (g != curg) {
                if (curg >= 0) atomicAdd(&g_gsum[curg], acc);
                curg = g;
                acc = 0.f;
            }
            acc += p;
        }
    }
    if (lane == 0 && curg >= 0) atomicAdd(&g_gsum[curg], acc);
}

// ---------------- finalize ----------------
__global__ void k_fin(float* __restrict__ out, const float* __restrict__ bfc) {
    int g = blockIdx.x * blockDim.x + threadIdx.x;
    if (g < N_GRAPHS) {
        float cnt = fmaxf((float)g_gcnt[g], 1.f);
        out[g] = g_gsum[g] / cnt + bfc[0];
    }
}

// ---------------- launch ----------------
extern "C" void kernel_launch(void* const* d_in, const int* in_sizes, int n_in,
                              void* d_out, int out_size) {
    const float* x     = (const float*)d_in[0];
    const int*   eidx  = (const int*)d_in[1];
    const int*   row   = eidx;
    const int*   col   = eidx + N_INC;
    const int*   batch = (const int*)d_in[2];
    const float* W1    = (const float*)d_in[3];
    const float* b1    = (const float*)d_in[4];
    const float* W2    = (const float*)d_in[5];
    const float* b2    = (const float*)d_in[6];
    const float* Wfc   = (const float*)d_in[7];
    const float* bfc   = (const float*)d_in[8];
    float*       out   = (float*)d_out;

    const int XT_SMEM  = (CH * WSTRIDE + 4 * 32 * WSTRIDE) * 4;   // 52224 B
    static bool attr_done = false;
    if (!attr_done) {
        cudaFuncSetAttribute(k_xt, cudaFuncAttributeMaxDynamicSharedMemorySize, XT_SMEM);
        attr_done = true;
    }

    const int NB_INC   = (N_INC + 255) / 256;          // 7813
    const int NB_XT    = (N_TILES / 2 + 3) / 4;        // 3907 (4 warps x 2 tiles)
    const int NB_MM    = (N_TILES + 3) / 4;            // 7813
    const int NB_EDGE  = N_HEDGES / 8;                 // 12500
    const int NB_CONVC = (N_NODES / 4) / 8;            // 15625

    k_zero<<<512, 256>>>();
    k_hist<<<NB_INC, 256>>>(row, col, batch);
    k_scan1m<<<NB_SCANN + NB_SCANE, 1024>>>();
    k_xt<<<NB_XT, 128, XT_SMEM>>>(x, W1, b1);   // position 4 -> gets the ncu capture
    k_scan2m<<<1, 512>>>();
    k_scan3m<<<NB_SCANN + NB_SCANE, 1024>>>();
    k_fill<<<NB_INC, 256>>>(row, col);
    k_edge<<<NB_EDGE, 256>>>();
    k_node<<<NB_MM, 128>>>(W2, b2);
    k_edge<<<NB_EDGE, 256>>>();
    k_conv_c<<<NB_CONVC, 256>>>(batch, Wfc);
    k_fin<<<2, 256>>>(out, bfc);
}